// round 9
// baseline (speedup 1.0000x reference)
#include <cuda_runtime.h>
#include <cstdint>

#define L  384
#define D  128
#define H  128
#define LL (L * L)   // 147456

// Scratch — static device globals (no cudaMalloc allowed).
__device__ float g_LhT[(size_t)H * LL];   // [h][i*L+k]  (tf32-rounded)
__device__ float g_RhT[(size_t)H * LL];   // [h][j*L+k]  (tf32-rounded, j-major)
__device__ float g_updT[(size_t)H * LL];  // [h][i*L+j]  (tf32-rounded)
__device__ float g_Wo2[D * H];            // [d][h] = tf32(W_out[d][h]) (native order)

// ---------------------------------------------------------------------------
// helpers
// ---------------------------------------------------------------------------
__device__ __forceinline__ unsigned f2tf(float x) {
    unsigned r; asm("cvt.rna.tf32.f32 %0, %1;" : "=r"(r) : "f"(x)); return r;
}
__device__ __forceinline__ float f2tff(float x) { return __uint_as_float(f2tf(x)); }

__device__ __forceinline__ void mma8(float c[4], const unsigned a[4], const unsigned b[2]) {
    asm volatile(
        "mma.sync.aligned.m16n8k8.row.col.f32.tf32.tf32.f32 "
        "{%0,%1,%2,%3}, {%4,%5,%6,%7}, {%8,%9}, {%0,%1,%2,%3};"
        : "+f"(c[0]), "+f"(c[1]), "+f"(c[2]), "+f"(c[3])
        : "r"(a[0]), "r"(a[1]), "r"(a[2]), "r"(a[3]), "r"(b[0]), "r"(b[1]));
}

// ldmatrix.x4 on fp32 data viewed as b16 8x8 matrices (8x4 fp32 tiles).
__device__ __forceinline__ void ldsm4(unsigned r[4], const float* p) {
    unsigned a = (unsigned)__cvta_generic_to_shared(p);
    asm volatile("ldmatrix.sync.aligned.m8n8.x4.shared.b16 {%0,%1,%2,%3}, [%4];"
                 : "=r"(r[0]), "=r"(r[1]), "=r"(r[2]), "=r"(r[3]) : "r"(a));
}

__device__ __forceinline__ void cpa16(void* dst, const void* src) {
    unsigned sa = (unsigned)__cvta_generic_to_shared(dst);
    asm volatile("cp.async.cg.shared.global [%0], [%1], 16;" :: "r"(sa), "l"(src));
}
__device__ __forceinline__ void cpa_commit() { asm volatile("cp.async.commit_group;"); }
__device__ __forceinline__ void cpa_wait1()  { asm volatile("cp.async.wait_group 1;"); }

// ---------------------------------------------------------------------------
// Kernel 0: tf32-round W_out (native [d][h] order) -> g_Wo2
// ---------------------------------------------------------------------------
__global__ __launch_bounds__(256) void k_wt(const float* __restrict__ Wo) {
    int idx = blockIdx.x * 256 + threadIdx.x;   // 16384
    g_Wo2[idx] = f2tff(Wo[idx]);
}

// ---------------------------------------------------------------------------
// Kernel 1: projection GEMM (tf32 mma), 4-warp CTAs.
//   isL: Lh(i, k=c, h) masked by mask[i*L+c]  -> g_LhT[h][i*L+c]
//   isR: Rh(k, j, h)   masked by mask[j*L+k]  -> g_RhT[h][j*L+k]  (j-major)
// Tile 64 rows x 128 h, BK=16, single-buffer smem + reg prefetch (2 syncs).
// Warp grid 2x2 of 32x64 tiles. 4 CTAs/SM.
// ---------------------------------------------------------------------------
#define PAS(k, m) sm[(k) * 72 + (m)]           // A [16][64] pitch 72
#define PBS(k, n) sm[1152 + (k) * 136 + (n)]   // B [16][128] pitch 136
#define PCS(n, m) sm[(n) * 68 + (m)]           // epilogue [32][64] pitch 68

__global__ __launch_bounds__(128, 4) void k_proj(
    const float* __restrict__ P, const float* __restrict__ mask,
    const float* __restrict__ Wl, const float* __restrict__ Wr)
{
    __shared__ __align__(16) float sm[3328];   // 13.3 KB
    float* mV = sm + 2240;                      // 64 mask vals (epilogue reuse)

    const int tid = threadIdx.x;
    const int wid = tid >> 5, lane = tid & 31;
    const int wm = wid & 1, wn = wid >> 1;
    const int group = lane >> 2, tid4 = lane & 3;
    const int bid = blockIdx.x;
    const bool isL = (blockIdx.y == 0);
    const float* __restrict__ W = isL ? Wl : Wr;

    int srcBase, srcStride, dmBase;
    if (isL) {
        srcBase = bid * 64;  srcStride = 1;  dmBase = bid * 64;
    } else {
        int j = bid / 6, k0p = (bid % 6) * 64;
        srcBase = k0p * L + j;  srcStride = L;  dmBase = j * L + k0p;
    }

    float acc[2][8][4];
#pragma unroll
    for (int mt = 0; mt < 2; mt++)
#pragma unroll
        for (int nt = 0; nt < 8; nt++)
#pragma unroll
            for (int v = 0; v < 4; v++) acc[mt][nt][v] = 0.f;

    float4 va[2], vb[4];
#define P_FETCH(k0)                                                                 \
    {                                                                               \
        _Pragma("unroll")                                                           \
        for (int p = 0; p < 2; p++) {                                               \
            int task = tid + p * 128;                                               \
            int r = task >> 2, q = (task & 3) * 4;                                  \
            va[p] = *(const float4*)&P[(size_t)(srcBase + (size_t)r * srcStride) * D + (k0) + q]; \
        }                                                                           \
        _Pragma("unroll")                                                           \
        for (int p = 0; p < 4; p++) {                                               \
            int task = tid + p * 128;                                               \
            int r = task >> 2, q = (task & 3) * 4;                                  \
            vb[p] = *(const float4*)&W[r * D + (k0) + q];                           \
        }                                                                           \
    }
#define P_STORE()                                                                   \
    {                                                                               \
        _Pragma("unroll")                                                           \
        for (int p = 0; p < 2; p++) {                                               \
            int task = tid + p * 128;                                               \
            int r = task >> 2, q = (task & 3) * 4;                                  \
            PAS(q + 0, r) = f2tff(va[p].x);                                         \
            PAS(q + 1, r) = f2tff(va[p].y);                                         \
            PAS(q + 2, r) = f2tff(va[p].z);                                         \
            PAS(q + 3, r) = f2tff(va[p].w);                                         \
        }                                                                           \
        _Pragma("unroll")                                                           \
        for (int p = 0; p < 4; p++) {                                               \
            int task = tid + p * 128;                                               \
            int r = task >> 2, q = (task & 3) * 4;                                  \
            PBS(q + 0, r) = f2tff(vb[p].x);                                         \
            PBS(q + 1, r) = f2tff(vb[p].y);                                         \
            PBS(q + 2, r) = f2tff(vb[p].z);                                         \
            PBS(q + 3, r) = f2tff(vb[p].w);                                         \
        }                                                                           \
    }

    P_FETCH(0);

#pragma unroll 1
    for (int it = 0; it < 8; it++) {
        __syncthreads();
        P_STORE();
        __syncthreads();
        if (it < 7) P_FETCH((it + 1) * 16);
#pragma unroll
        for (int ks = 0; ks < 2; ks++) {
            int k = ks * 8;
            unsigned a[2][4], b[8][2];
#pragma unroll
            for (int mt = 0; mt < 2; mt++) {
                int r = wm * 32 + mt * 16 + group;
                a[mt][0] = __float_as_uint(PAS(k + tid4, r));
                a[mt][1] = __float_as_uint(PAS(k + tid4, r + 8));
                a[mt][2] = __float_as_uint(PAS(k + tid4 + 4, r));
                a[mt][3] = __float_as_uint(PAS(k + tid4 + 4, r + 8));
            }
#pragma unroll
            for (int nt = 0; nt < 8; nt++) {
                int c = wn * 64 + nt * 8 + group;
                b[nt][0] = __float_as_uint(PBS(k + tid4, c));
                b[nt][1] = __float_as_uint(PBS(k + tid4 + 4, c));
            }
#pragma unroll
            for (int mt = 0; mt < 2; mt++)
#pragma unroll
                for (int nt = 0; nt < 8; nt++)
                    mma8(acc[mt][nt], a[mt], b[nt]);
        }
    }
#undef P_FETCH
#undef P_STORE

    __syncthreads();
    if (tid < 64) mV[tid] = mask[dmBase + tid];
    float* __restrict__ dst = isL ? g_LhT : g_RhT;

    // Epilogue: 4 chunks of 32 h, staged transposed ([h][m]) then coalesced.
#pragma unroll 1
    for (int nc = 0; nc < 4; nc++) {
        __syncthreads();
        if (wn == (nc >> 1)) {
#pragma unroll
            for (int nt2 = 0; nt2 < 4; nt2++) {
                int nt = (nc & 1) * 4 + nt2;
                int cc = nt2 * 8 + 2 * tid4;
#pragma unroll
                for (int mt = 0; mt < 2; mt++) {
                    int r = wm * 32 + mt * 16 + group;
                    PCS(cc,     r)     = acc[mt][nt][0];
                    PCS(cc + 1, r)     = acc[mt][nt][1];
                    PCS(cc,     r + 8) = acc[mt][nt][2];
                    PCS(cc + 1, r + 8) = acc[mt][nt][3];
                }
            }
        }
        __syncthreads();
#pragma unroll
        for (int p = 0; p < 4; p++) {
            int task = tid + p * 128;
            int nr = task >> 4, m = (task & 15) * 4;
            float4 o;
            o.x = f2tff(PCS(nr, m + 0) * mV[m + 0]);
            o.y = f2tff(PCS(nr, m + 1) * mV[m + 1]);
            o.z = f2tff(PCS(nr, m + 2) * mV[m + 2]);
            o.w = f2tff(PCS(nr, m + 3) * mV[m + 3]);
            *(float4*)&dst[(size_t)(nc * 32 + nr) * LL + dmBase + m] = o;
        }
    }
#undef PAS
#undef PBS
#undef PCS
}

// ---------------------------------------------------------------------------
// Kernel 2: triangle einsum (tf32 mma + ldmatrix), 4-warp CTAs.
// Tile 64(i) x 128(j), BK=16, 2-stage cp.async. Warp grid 2x2 of 32x64.
// A [m][16] pitch 20, B [n][16] pitch 20. 4 CTAs/SM.
// ---------------------------------------------------------------------------
#define T_STG 3840                    // floats: A 64*20 + B 128*20
#define TAS(s, m, k) sm[(s) * T_STG + (m) * 20 + (k)]
#define TBS(s, n, k) sm[(s) * T_STG + 1280 + (n) * 20 + (k)]
#define TCS(m, j)    sm[(m) * 132 + (j)]     // epilogue [32][128] pitch 132

__global__ __launch_bounds__(128, 4) void k_tri() {
    __shared__ __align__(16) float sm[2 * T_STG];   // 30.7 KB

    const int tid = threadIdx.x;
    const int wid = tid >> 5, lane = tid & 31;
    const int wm = wid & 1, wn = wid >> 1;
    const int group = lane >> 2, tid4 = lane & 3;
    const size_t hoff = (size_t)blockIdx.z * LL;
    const int i0 = blockIdx.y * 64;
    const int j0 = blockIdx.x * 128;

    const float* __restrict__ A = g_LhT + hoff;
    const float* __restrict__ B = g_RhT + hoff;

    int aOff[2], bOff[4];
#pragma unroll
    for (int mt = 0; mt < 2; mt++)
        aOff[mt] = (wm * 32 + mt * 16 + (lane & 7) + 8 * ((lane >> 3) & 1)) * 20
                 + 4 * (lane >> 4);
#pragma unroll
    for (int p = 0; p < 4; p++)
        bOff[p] = 1280 + (wn * 64 + p * 16 + (lane & 7) + 8 * (lane >> 4)) * 20
                + 4 * ((lane >> 3) & 1);

    float acc[2][8][4];
#pragma unroll
    for (int mt = 0; mt < 2; mt++)
#pragma unroll
        for (int nt = 0; nt < 8; nt++)
#pragma unroll
            for (int v = 0; v < 4; v++) acc[mt][nt][v] = 0.f;

#define T_LOAD(s, k0)                                                          \
    {                                                                          \
        _Pragma("unroll")                                                      \
        for (int p = 0; p < 2; p++) {                                          \
            int task = tid + p * 128;                                          \
            int r = task >> 2, q = task & 3;                                   \
            cpa16(&TAS(s, r, q * 4), &A[(size_t)(i0 + r) * L + (k0) + q * 4]); \
        }                                                                      \
        _Pragma("unroll")                                                      \
        for (int p = 0; p < 4; p++) {                                          \
            int task = tid + p * 128;                                          \
            int r = task >> 2, q = task & 3;                                   \
            cpa16(&TBS(s, r, q * 4), &B[(size_t)(j0 + r) * L + (k0) + q * 4]); \
        }                                                                      \
    }

    T_LOAD(0, 0);  cpa_commit();
    T_LOAD(1, 16); cpa_commit();

#pragma unroll 2
    for (int it = 0; it < 24; it++) {
        const int s = it & 1;
        cpa_wait1();
        __syncthreads();
#pragma unroll
        for (int ks = 0; ks < 2; ks++) {
            const int k = ks * 8;
            unsigned a[2][4], b[4][4];
#pragma unroll
            for (int mt = 0; mt < 2; mt++)
                ldsm4(a[mt], &sm[s * T_STG + aOff[mt] + k]);
#pragma unroll
            for (int p = 0; p < 4; p++)
                ldsm4(b[p], &sm[s * T_STG + bOff[p] + k]);
#pragma unroll
            for (int mt = 0; mt < 2; mt++)
#pragma unroll
                for (int p = 0; p < 4; p++) {
                    mma8(acc[mt][2 * p],     a[mt], &b[p][0]);
                    mma8(acc[mt][2 * p + 1], a[mt], &b[p][2]);
                }
        }
        __syncthreads();
        if (it + 2 < 24) T_LOAD(s, (it + 2) * 16);
        cpa_commit();
    }
#undef T_LOAD

    // Epilogue: two 32-row chunks staged through smem, coalesced tf32 store.
#pragma unroll 1
    for (int mc = 0; mc < 2; mc++) {
        __syncthreads();
        if (wm == mc) {
#pragma unroll
            for (int nt = 0; nt < 8; nt++) {
                int cc = wn * 64 + nt * 8 + 2 * tid4;
#pragma unroll
                for (int mt = 0; mt < 2; mt++) {
                    int r = mt * 16 + group;
                    TCS(r,     cc)     = acc[mt][nt][0];
                    TCS(r,     cc + 1) = acc[mt][nt][1];
                    TCS(r + 8, cc)     = acc[mt][nt][2];
                    TCS(r + 8, cc + 1) = acc[mt][nt][3];
                }
            }
        }
        __syncthreads();
#pragma unroll
        for (int p = 0; p < 8; p++) {
            int task = tid + p * 128;
            int row = task >> 5, j = (task & 31) * 4;
            float4 o;
            o.x = f2tff(TCS(row, j + 0));
            o.y = f2tff(TCS(row, j + 1));
            o.z = f2tff(TCS(row, j + 2));
            o.w = f2tff(TCS(row, j + 3));
            *(float4*)&g_updT[hoff + (size_t)(i0 + mc * 32 + row) * L + j0 + j] = o;
        }
    }
#undef TAS
#undef TBS
#undef TCS
}

// ---------------------------------------------------------------------------
// Kernel 3: output projection + residual + mask + LayerNorm.
// (round-8 version, committed: 91.9 us)
// ---------------------------------------------------------------------------
#define F_STG 3712                    // floats: A 16*72 + B 128*20
#define FAS(s, k, m) sm[(s) * F_STG + (k) * 72 + (m)]
#define FBS(s, n, k) sm[(s) * F_STG + 1152 + (n) * 20 + (k)]
#define FCS(m, d)    sm[(m) * 132 + (d)]

__global__ __launch_bounds__(128, 4) void k_fin(
    const float* __restrict__ P, const float* __restrict__ mask,
    const float* __restrict__ gamma, const float* __restrict__ beta,
    float* __restrict__ out)
{
    __shared__ __align__(16) float sm[8448];   // max(2*F_STG=7424, 64*132=8448)

    const int tid = threadIdx.x;
    const int wid = tid >> 5, lane = tid & 31;
    const int wm = wid & 1, wn = wid >> 1;
    const int group = lane >> 2, tid4 = lane & 3;
    const int pairBase = blockIdx.x * 64;

    int bOff[4];
#pragma unroll
    for (int p = 0; p < 4; p++)
        bOff[p] = 1152 + (wn * 64 + p * 16 + (lane & 7) + 8 * (lane >> 4)) * 20
                + 4 * ((lane >> 3) & 1);

    float acc[2][8][4];
#pragma unroll
    for (int mt = 0; mt < 2; mt++)
#pragma unroll
        for (int nt = 0; nt < 8; nt++)
#pragma unroll
            for (int v = 0; v < 4; v++) acc[mt][nt][v] = 0.f;

#define F_LOAD(s, k0)                                                                \
    {                                                                                \
        _Pragma("unroll")                                                            \
        for (int p = 0; p < 2; p++) {                                                \
            int task = tid + p * 128;                                                \
            int k = task >> 4, m4 = (task & 15) * 4;                                 \
            cpa16(&FAS(s, k, m4), &g_updT[(size_t)((k0) + k) * LL + pairBase + m4]); \
        }                                                                            \
        _Pragma("unroll")                                                            \
        for (int p = 0; p < 4; p++) {                                                \
            int task = tid + p * 128;                                                \
            int n = task >> 2, q = (task & 3) * 4;                                   \
            cpa16(&FBS(s, n, q), &g_Wo2[n * H + (k0) + q]);                          \
        }                                                                            \
    }

    F_LOAD(0, 0);  cpa_commit();
    F_LOAD(1, 16); cpa_commit();

#pragma unroll 1
    for (int it = 0; it < 8; it++) {
        const int s = it & 1;
        cpa_wait1();
        __syncthreads();
#pragma unroll
        for (int ks = 0; ks < 2; ks++) {
            const int k = ks * 8;
            unsigned a[2][4], b[4][4];
#pragma unroll
            for (int mt = 0; mt < 2; mt++) {
                int r = wm * 32 + mt * 16 + group;
                a[mt][0] = __float_as_uint(FAS(s, k + tid4,     r));
                a[mt][1] = __float_as_uint(FAS(s, k + tid4,     r + 8));
                a[mt][2] = __float_as_uint(FAS(s, k + tid4 + 4, r));
                a[mt][3] = __float_as_uint(FAS(s, k + tid4 + 4, r + 8));
            }
#pragma unroll
            for (int p = 0; p < 4; p++)
                ldsm4(b[p], &sm[s * F_STG + bOff[p] + k]);
#pragma unroll
            for (int mt = 0; mt < 2; mt++)
#pragma unroll
                for (int p = 0; p < 4; p++) {
                    mma8(acc[mt][2 * p],     a[mt], &b[p][0]);
                    mma8(acc[mt][2 * p + 1], a[mt], &b[p][2]);
                }
        }
        __syncthreads();
        if (it + 2 < 8) F_LOAD(s, (it + 2) * 16);
        cpa_commit();
    }

    // Epilogue: stage whole 64x128 acc tile -> smem, then LayerNorm.
    __syncthreads();
#pragma unroll
    for (int nt = 0; nt < 8; nt++) {
        int cc = wn * 64 + nt * 8 + 2 * tid4;
#pragma unroll
        for (int mt = 0; mt < 2; mt++) {
            int r = wm * 32 + mt * 16 + group;
            FCS(r,     cc)     = acc[mt][nt][0];
            FCS(r,     cc + 1) = acc[mt][nt][1];
            FCS(r + 8, cc)     = acc[mt][nt][2];
            FCS(r + 8, cc + 1) = acc[mt][nt][3];
        }
    }
    __syncthreads();

    // LayerNorm: 4 threads per pair-row (32 d each), two passes of 32 rows.
#pragma unroll 1
    for (int h2 = 0; h2 < 2; h2++) {
        const int row = (tid >> 2) + h2 * 32;
        const int q   = tid & 3;
        const int pair = pairBase + row;
        const float mk = mask[pair];

        float pn[32];
        float s = 0.f, sq = 0.f;
#pragma unroll
        for (int u = 0; u < 8; u++) {
            float4 pv = *(const float4*)&P[(size_t)pair * D + q * 32 + 4 * u];
            pn[4 * u + 0] = pv.x + mk * FCS(row, q * 32 + 4 * u + 0);
            pn[4 * u + 1] = pv.y + mk * FCS(row, q * 32 + 4 * u + 1);
            pn[4 * u + 2] = pv.z + mk * FCS(row, q * 32 + 4 * u + 2);
            pn[4 * u + 3] = pv.w + mk * FCS(row, q * 32 + 4 * u + 3);
        }
#pragma unroll
        for (int v = 0; v < 32; v++) { s += pn[v]; sq = fmaf(pn[v], pn[v], sq); }
        s  += __shfl_down_sync(0xffffffffu, s,  2, 4);
        s  += __shfl_down_sync(0xffffffffu, s,  1, 4);
        sq += __shfl_down_sync(0xffffffffu, sq, 2, 4);
        sq += __shfl_down_sync(0xffffffffu, sq, 1, 4);
        s  = __shfl_sync(0xffffffffu, s,  0, 4);
        sq = __shfl_sync(0xffffffffu, sq, 0, 4);

        const float mu  = s * (1.f / 128.f);
        const float var = sq * (1.f / 128.f) - mu * mu;
        const float inv = rsqrtf(var + 1e-5f);

#pragma unroll
        for (int u = 0; u < 8; u++) {
            int d = q * 32 + 4 * u;
            float4 gv = *(const float4*)&gamma[d];
            float4 bv = *(const float4*)&beta[d];
            float4 o;
            o.x = (pn[4 * u + 0] - mu) * inv * gv.x + bv.x;
            o.y = (pn[4 * u + 1] - mu) * inv * gv.y + bv.y;
            o.z = (pn[4 * u + 2] - mu) * inv * gv.z + bv.z;
            o.w = (pn[4 * u + 3] - mu) * inv * gv.w + bv.w;
            *(float4*)&out[(size_t)pair * D + d] = o;
        }
    }
#undef F_LOAD
}
#undef FAS
#undef FBS
#undef FCS

// ---------------------------------------------------------------------------
extern "C" void kernel_launch(void* const* d_in, const int* in_sizes, int n_in,
                              void* d_out, int out_size) {
    const float* P     = (const float*)d_in[0];
    const float* mask  = (const float*)d_in[1];
    const float* Wl    = (const float*)d_in[2];
    const float* Wr    = (const float*)d_in[3];
    const float* Wo    = (const float*)d_in[4];
    const float* gamma = (const float*)d_in[5];
    const float* beta  = (const float*)d_in[6];
    float* out = (float*)d_out;

    k_wt<<<64, 256>>>(Wo);
    k_proj<<<dim3(LL / 64, 2), 128>>>(P, mask, Wl, Wr);
    k_tri<<<dim3(L / 128, L / 64, H), 128>>>();
    k_fin<<<LL / 64, 128>>>(P, mask, gamma, beta, out);
}

// round 10
// speedup vs baseline: 1.7027x; 1.7027x over previous
#include <cuda_runtime.h>
#include <cuda_fp16.h>
#include <cstdint>

#define L  384
#define D  128
#define H  128
#define LL (L * L)   // 147456

// Scratch — static device globals (no cudaMalloc allowed).
__device__ __half g_LhT[(size_t)H * LL];  // [h][i*L+k]  (fp16, 10-bit mantissa = tf32)
__device__ __half g_RhT[(size_t)H * LL];  // [h][j*L+k]  (fp16, j-major)
__device__ float  g_updT[(size_t)H * LL]; // [h][i*L+j]  (tf32-rounded fp32)
__device__ float  g_Wo2[D * H];           // [d][h] = tf32(W_out[d][h]) (native order)

// ---------------------------------------------------------------------------
// helpers
// ---------------------------------------------------------------------------
__device__ __forceinline__ unsigned f2tf(float x) {
    unsigned r; asm("cvt.rna.tf32.f32 %0, %1;" : "=r"(r) : "f"(x)); return r;
}
__device__ __forceinline__ float f2tff(float x) { return __uint_as_float(f2tf(x)); }

__device__ __forceinline__ void mma8(float c[4], const unsigned a[4], const unsigned b[2]) {
    asm volatile(
        "mma.sync.aligned.m16n8k8.row.col.f32.tf32.tf32.f32 "
        "{%0,%1,%2,%3}, {%4,%5,%6,%7}, {%8,%9}, {%0,%1,%2,%3};"
        : "+f"(c[0]), "+f"(c[1]), "+f"(c[2]), "+f"(c[3])
        : "r"(a[0]), "r"(a[1]), "r"(a[2]), "r"(a[3]), "r"(b[0]), "r"(b[1]));
}

// fp16 mma, fp32 accumulate
__device__ __forceinline__ void mma16(float c[4], const unsigned a[4], const unsigned b[2]) {
    asm volatile(
        "mma.sync.aligned.m16n8k16.row.col.f32.f16.f16.f32 "
        "{%0,%1,%2,%3}, {%4,%5,%6,%7}, {%8,%9}, {%0,%1,%2,%3};"
        : "+f"(c[0]), "+f"(c[1]), "+f"(c[2]), "+f"(c[3])
        : "r"(a[0]), "r"(a[1]), "r"(a[2]), "r"(a[3]), "r"(b[0]), "r"(b[1]));
}

// ldmatrix.x4 (b16 8x8 matrices)
__device__ __forceinline__ void ldsm4f(unsigned r[4], const float* p) {
    unsigned a = (unsigned)__cvta_generic_to_shared(p);
    asm volatile("ldmatrix.sync.aligned.m8n8.x4.shared.b16 {%0,%1,%2,%3}, [%4];"
                 : "=r"(r[0]), "=r"(r[1]), "=r"(r[2]), "=r"(r[3]) : "r"(a));
}
__device__ __forceinline__ void ldsm4h(unsigned r[4], const __half* p) {
    unsigned a = (unsigned)__cvta_generic_to_shared(p);
    asm volatile("ldmatrix.sync.aligned.m8n8.x4.shared.b16 {%0,%1,%2,%3}, [%4];"
                 : "=r"(r[0]), "=r"(r[1]), "=r"(r[2]), "=r"(r[3]) : "r"(a));
}

__device__ __forceinline__ void cpa16(void* dst, const void* src) {
    unsigned sa = (unsigned)__cvta_generic_to_shared(dst);
    asm volatile("cp.async.cg.shared.global [%0], [%1], 16;" :: "r"(sa), "l"(src));
}
__device__ __forceinline__ void cpa_commit() { asm volatile("cp.async.commit_group;"); }
__device__ __forceinline__ void cpa_wait1()  { asm volatile("cp.async.wait_group 1;"); }

// ---------------------------------------------------------------------------
// Kernel 0: tf32-round W_out (native [d][h] order) -> g_Wo2
// ---------------------------------------------------------------------------
__global__ __launch_bounds__(256) void k_wt(const float* __restrict__ Wo) {
    int idx = blockIdx.x * 256 + threadIdx.x;   // 16384
    g_Wo2[idx] = f2tff(Wo[idx]);
}

// ---------------------------------------------------------------------------
// Kernel 1: projection GEMM (tf32 mma), round-6/8 structure, fp16 output.
//   isL: Lh(i, k=c, h) masked by mask[i*L+c]  -> g_LhT[h][i*L+c]
//   isR: Rh(k, j, h)   masked by mask[j*L+k]  -> g_RhT[h][j*L+k]  (j-major)
// ---------------------------------------------------------------------------
__global__ __launch_bounds__(256) void k_proj(
    const float* __restrict__ P, const float* __restrict__ mask,
    const float* __restrict__ Wl, const float* __restrict__ Wr)
{
    __shared__ __align__(16) float sm[8768];
#define PAS(k, m) sm[(k) * 137 + (m)]
#define PBS(k, n) sm[32 * 137 + (k) * 137 + (n)]
#define PCS(n, m) sm[(n) * 132 + (m)]
    float* mV = sm + 32 * 132 + 16;

    const int tid = threadIdx.x;
    const int wid = tid >> 5, lane = tid & 31;
    const int wm = wid & 3, wn = wid >> 2;
    const int group = lane >> 2, tid4 = lane & 3;
    const int bid = blockIdx.x;
    const bool isL = (blockIdx.y == 0);
    const float* __restrict__ W = isL ? Wl : Wr;

    int srcBase, srcStride, dmBase;
    if (isL) {
        srcBase = bid * 128;  srcStride = 1;  dmBase = bid * 128;
    } else {
        int j = bid / 3, k0p = (bid % 3) * 128;
        srcBase = k0p * L + j;  srcStride = L;  dmBase = j * L + k0p;
    }

    float acc[2][8][4];
#pragma unroll
    for (int mt = 0; mt < 2; mt++)
#pragma unroll
        for (int nt = 0; nt < 8; nt++)
#pragma unroll
            for (int v = 0; v < 4; v++) acc[mt][nt][v] = 0.f;

    const int mld = tid >> 3;
    const int kld = (tid & 7) * 4;

    float4 va[4], vb[4];
#pragma unroll
    for (int p = 0; p < 4; p++) {
        va[p] = *(const float4*)&P[(size_t)(srcBase + (size_t)(mld + p * 32) * srcStride) * D + kld];
        vb[p] = *(const float4*)&W[(mld + p * 32) * D + kld];
    }

#pragma unroll
    for (int it = 0; it < 4; it++) {
        __syncthreads();
#pragma unroll
        for (int p = 0; p < 4; p++) {
            int m = mld + p * 32;
            PAS(kld + 0, m) = f2tff(va[p].x);
            PAS(kld + 1, m) = f2tff(va[p].y);
            PAS(kld + 2, m) = f2tff(va[p].z);
            PAS(kld + 3, m) = f2tff(va[p].w);
            PBS(kld + 0, m) = f2tff(vb[p].x);
            PBS(kld + 1, m) = f2tff(vb[p].y);
            PBS(kld + 2, m) = f2tff(vb[p].z);
            PBS(kld + 3, m) = f2tff(vb[p].w);
        }
        __syncthreads();
        if (it < 3) {
            int k0 = (it + 1) * 32;
#pragma unroll
            for (int p = 0; p < 4; p++) {
                va[p] = *(const float4*)&P[(size_t)(srcBase + (size_t)(mld + p * 32) * srcStride) * D + k0 + kld];
                vb[p] = *(const float4*)&W[(mld + p * 32) * D + k0 + kld];
            }
        }
#pragma unroll
        for (int ks = 0; ks < 4; ks++) {
            int k = ks * 8;
            unsigned a[2][4], b[8][2];
#pragma unroll
            for (int mt = 0; mt < 2; mt++) {
                int r = wm * 32 + mt * 16 + group;
                a[mt][0] = __float_as_uint(PAS(k + tid4, r));
                a[mt][1] = __float_as_uint(PAS(k + tid4, r + 8));
                a[mt][2] = __float_as_uint(PAS(k + tid4 + 4, r));
                a[mt][3] = __float_as_uint(PAS(k + tid4 + 4, r + 8));
            }
#pragma unroll
            for (int nt = 0; nt < 8; nt++) {
                int c = wn * 64 + nt * 8 + group;
                b[nt][0] = __float_as_uint(PBS(k + tid4, c));
                b[nt][1] = __float_as_uint(PBS(k + tid4 + 4, c));
            }
#pragma unroll
            for (int mt = 0; mt < 2; mt++)
#pragma unroll
                for (int nt = 0; nt < 8; nt++)
                    mma8(acc[mt][nt], a[mt], b[nt]);
        }
    }

    __syncthreads();
    if (tid < 128) mV[tid] = mask[dmBase + tid];
    __half* __restrict__ dst = isL ? g_LhT : g_RhT;

#pragma unroll
    for (int nc = 0; nc < 4; nc++) {
        __syncthreads();
        if (wn == (nc >> 1)) {
#pragma unroll
            for (int nt2 = 0; nt2 < 4; nt2++) {
                int nt = (nc & 1) * 4 + nt2;
                int cc = nt2 * 8 + 2 * tid4;
#pragma unroll
                for (int mt = 0; mt < 2; mt++) {
                    int r = wm * 32 + mt * 16 + group;
                    PCS(cc,     r)     = acc[mt][nt][0];
                    PCS(cc + 1, r)     = acc[mt][nt][1];
                    PCS(cc,     r + 8) = acc[mt][nt][2];
                    PCS(cc + 1, r + 8) = acc[mt][nt][3];
                }
            }
        }
        __syncthreads();
#pragma unroll
        for (int p = 0; p < 4; p++) {
            int nr = (tid >> 5) + p * 8;
            int m  = (tid & 31) * 4;
            __half2 h0 = __floats2half2_rn(PCS(nr, m + 0) * mV[m + 0],
                                           PCS(nr, m + 1) * mV[m + 1]);
            __half2 h1 = __floats2half2_rn(PCS(nr, m + 2) * mV[m + 2],
                                           PCS(nr, m + 3) * mV[m + 3]);
            uint2 u = make_uint2(*(unsigned*)&h0, *(unsigned*)&h1);
            *(uint2*)&dst[(size_t)(nc * 32 + nr) * LL + dmBase + m] = u;
        }
    }
#undef PAS
#undef PBS
#undef PCS
}

// ---------------------------------------------------------------------------
// Kernel 2: triangle einsum — fp16 mma.m16n8k16 + ldmatrix.
//   updT[h][i][j] = sum_k LhT[h][i][k] * RhT[h][j][k]
// Block 128x128, BK=32 (fp16), 2-stage cp.async, 8 warps (32x64 tiles).
// Tiles [row][32] halves, pitch 40 halves (80B, conflict-free as before).
// ---------------------------------------------------------------------------
#define T_STG 10240                   // halves per stage: A 128*40 + B 128*40
#define TCS(m, j)    smf[(m) * 132 + (j)]

__global__ __launch_bounds__(256, 2) void k_tri() {
    __shared__ __align__(16) float smf[10240];   // 40,960 B
    __half* sm = (__half*)smf;

    const int tid = threadIdx.x;
    const int wid = tid >> 5, lane = tid & 31;
    const int wm = wid & 3, wn = wid >> 2;
    const int group = lane >> 2, tid4 = lane & 3;
    const size_t hoff = (size_t)blockIdx.z * LL;
    const int i0 = blockIdx.y * 128;
    const int j0 = blockIdx.x * 128;

    const __half* __restrict__ A = g_LhT + hoff;
    const __half* __restrict__ B = g_RhT + hoff;

    // ldmatrix offsets (halves within a stage); same mapping as validated
    // tf32-as-b16 pattern, now native fp16.
    int aOff[2], bOff[4];
#pragma unroll
    for (int mt = 0; mt < 2; mt++)
        aOff[mt] = (wm * 32 + mt * 16 + (lane & 7) + 8 * ((lane >> 3) & 1)) * 40
                 + 8 * (lane >> 4);
#pragma unroll
    for (int p = 0; p < 4; p++)
        bOff[p] = 5120 + (wn * 64 + p * 16 + (lane & 7) + 8 * (lane >> 4)) * 40
                + 8 * ((lane >> 3) & 1);

    float acc[2][8][4];
#pragma unroll
    for (int mt = 0; mt < 2; mt++)
#pragma unroll
        for (int nt = 0; nt < 8; nt++)
#pragma unroll
            for (int v = 0; v < 4; v++) acc[mt][nt][v] = 0.f;

    // stage loader: 512 cpa16 A + 512 cpa16 B (4 per thread), k0 in halves.
#define T_LOAD(s, k0)                                                              \
    {                                                                              \
        _Pragma("unroll")                                                          \
        for (int p = 0; p < 2; p++) {                                              \
            int task = tid + p * 256;                                              \
            int r = task >> 2, q = task & 3;                                       \
            cpa16(&sm[(s) * T_STG + r * 40 + q * 8],                               \
                  &A[(size_t)(i0 + r) * L + (k0) + q * 8]);                        \
            cpa16(&sm[(s) * T_STG + 5120 + r * 40 + q * 8],                        \
                  &B[(size_t)(j0 + r) * L + (k0) + q * 8]);                        \
        }                                                                          \
    }

    T_LOAD(0, 0);  cpa_commit();
    T_LOAD(1, 32); cpa_commit();

#pragma unroll 2
    for (int it = 0; it < 12; it++) {
        const int s = it & 1;
        cpa_wait1();
        __syncthreads();
#pragma unroll
        for (int ks = 0; ks < 2; ks++) {
            const int k = ks * 16;
            unsigned a[2][4], b[4][4];
#pragma unroll
            for (int mt = 0; mt < 2; mt++)
                ldsm4h(a[mt], &sm[s * T_STG + aOff[mt] + k]);
#pragma unroll
            for (int p = 0; p < 4; p++)
                ldsm4h(b[p], &sm[s * T_STG + bOff[p] + k]);
#pragma unroll
            for (int mt = 0; mt < 2; mt++)
#pragma unroll
                for (int p = 0; p < 4; p++) {
                    mma16(acc[mt][2 * p],     a[mt], &b[p][0]);
                    mma16(acc[mt][2 * p + 1], a[mt], &b[p][2]);
                }
        }
        __syncthreads();
        if (it + 2 < 12) T_LOAD(s, (it + 2) * 32);
        cpa_commit();
    }
#undef T_LOAD

    // Epilogue: two 64-row chunks staged through smem, coalesced tf32 store.
#pragma unroll 1
    for (int mc = 0; mc < 2; mc++) {
        __syncthreads();
        if ((wm >> 1) == mc) {
#pragma unroll
            for (int nt = 0; nt < 8; nt++) {
                int cc = wn * 64 + nt * 8 + 2 * tid4;
#pragma unroll
                for (int mt = 0; mt < 2; mt++) {
                    int r = (wm & 1) * 32 + mt * 16 + group;
                    TCS(r,     cc)     = acc[mt][nt][0];
                    TCS(r,     cc + 1) = acc[mt][nt][1];
                    TCS(r + 8, cc)     = acc[mt][nt][2];
                    TCS(r + 8, cc + 1) = acc[mt][nt][3];
                }
            }
        }
        __syncthreads();
#pragma unroll
        for (int p = 0; p < 8; p++) {
            int row = (tid >> 5) + p * 8;
            int j   = (tid & 31) * 4;
            float4 o;
            o.x = f2tff(TCS(row, j + 0));
            o.y = f2tff(TCS(row, j + 1));
            o.z = f2tff(TCS(row, j + 2));
            o.w = f2tff(TCS(row, j + 3));
            *(float4*)&g_updT[hoff + (size_t)(i0 + mc * 64 + row) * L + j0 + j] = o;
        }
    }
#undef TCS
}

// ---------------------------------------------------------------------------
// Kernel 3: output projection + residual + mask + LayerNorm.
// (round-8 version, committed: 91.9 us — unchanged)
// ---------------------------------------------------------------------------
#define F_STG 3712                    // floats: A 16*72 + B 128*20
#define FAS(s, k, m) sm[(s) * F_STG + (k) * 72 + (m)]
#define FBS(s, n, k) sm[(s) * F_STG + 1152 + (n) * 20 + (k)]
#define FCS(m, d)    sm[(m) * 132 + (d)]

__global__ __launch_bounds__(128, 4) void k_fin(
    const float* __restrict__ P, const float* __restrict__ mask,
    const float* __restrict__ gamma, const float* __restrict__ beta,
    float* __restrict__ out)
{
    __shared__ __align__(16) float sm[8448];

    const int tid = threadIdx.x;
    const int wid = tid >> 5, lane = tid & 31;
    const int wm = wid & 1, wn = wid >> 1;
    const int group = lane >> 2, tid4 = lane & 3;
    const int pairBase = blockIdx.x * 64;

    int bOff[4];
#pragma unroll
    for (int p = 0; p < 4; p++)
        bOff[p] = 1152 + (wn * 64 + p * 16 + (lane & 7) + 8 * (lane >> 4)) * 20
                + 4 * ((lane >> 3) & 1);

    float acc[2][8][4];
#pragma unroll
    for (int mt = 0; mt < 2; mt++)
#pragma unroll
        for (int nt = 0; nt < 8; nt++)
#pragma unroll
            for (int v = 0; v < 4; v++) acc[mt][nt][v] = 0.f;

#define F_LOAD(s, k0)                                                                \
    {                                                                                \
        _Pragma("unroll")                                                            \
        for (int p = 0; p < 2; p++) {                                                \
            int task = tid + p * 128;                                                \
            int k = task >> 4, m4 = (task & 15) * 4;                                 \
            cpa16(&FAS(s, k, m4), &g_updT[(size_t)((k0) + k) * LL + pairBase + m4]); \
        }                                                                            \
        _Pragma("unroll")                                                            \
        for (int p = 0; p < 4; p++) {                                                \
            int task = tid + p * 128;                                                \
            int n = task >> 2, q = (task & 3) * 4;                                   \
            cpa16(&FBS(s, n, q), &g_Wo2[n * H + (k0) + q]);                          \
        }                                                                            \
    }

    F_LOAD(0, 0);  cpa_commit();
    F_LOAD(1, 16); cpa_commit();

#pragma unroll 1
    for (int it = 0; it < 8; it++) {
        const int s = it & 1;
        cpa_wait1();
        __syncthreads();
#pragma unroll
        for (int ks = 0; ks < 2; ks++) {
            const int k = ks * 8;
            unsigned a[2][4], b[4][4];
#pragma unroll
            for (int mt = 0; mt < 2; mt++) {
                int r = wm * 32 + mt * 16 + group;
                a[mt][0] = __float_as_uint(FAS(s, k + tid4,     r));
                a[mt][1] = __float_as_uint(FAS(s, k + tid4,     r + 8));
                a[mt][2] = __float_as_uint(FAS(s, k + tid4 + 4, r));
                a[mt][3] = __float_as_uint(FAS(s, k + tid4 + 4, r + 8));
            }
#pragma unroll
            for (int p = 0; p < 4; p++)
                ldsm4f(b[p], &sm[s * F_STG + bOff[p] + k]);
#pragma unroll
            for (int mt = 0; mt < 2; mt++)
#pragma unroll
                for (int p = 0; p < 4; p++) {
                    mma8(acc[mt][2 * p],     a[mt], &b[p][0]);
                    mma8(acc[mt][2 * p + 1], a[mt], &b[p][2]);
                }
        }
        __syncthreads();
        if (it + 2 < 8) F_LOAD(s, (it + 2) * 16);
        cpa_commit();
    }

    __syncthreads();
#pragma unroll
    for (int nt = 0; nt < 8; nt++) {
        int cc = wn * 64 + nt * 8 + 2 * tid4;
#pragma unroll
        for (int mt = 0; mt < 2; mt++) {
            int r = wm * 32 + mt * 16 + group;
            FCS(r,     cc)     = acc[mt][nt][0];
            FCS(r,     cc + 1) = acc[mt][nt][1];
            FCS(r + 8, cc)     = acc[mt][nt][2];
            FCS(r + 8, cc + 1) = acc[mt][nt][3];
        }
    }
    __syncthreads();

#pragma unroll 1
    for (int h2 = 0; h2 < 2; h2++) {
        const int row = (tid >> 2) + h2 * 32;
        const int q   = tid & 3;
        const int pair = pairBase + row;
        const float mk = mask[pair];

        float pn[32];
        float s = 0.f, sq = 0.f;
#pragma unroll
        for (int u = 0; u < 8; u++) {
            float4 pv = *(const float4*)&P[(size_t)pair * D + q * 32 + 4 * u];
            pn[4 * u + 0] = pv.x + mk * FCS(row, q * 32 + 4 * u + 0);
            pn[4 * u + 1] = pv.y + mk * FCS(row, q * 32 + 4 * u + 1);
            pn[4 * u + 2] = pv.z + mk * FCS(row, q * 32 + 4 * u + 2);
            pn[4 * u + 3] = pv.w + mk * FCS(row, q * 32 + 4 * u + 3);
        }
#pragma unroll
        for (int v = 0; v < 32; v++) { s += pn[v]; sq = fmaf(pn[v], pn[v], sq); }
        s  += __shfl_down_sync(0xffffffffu, s,  2, 4);
        s  += __shfl_down_sync(0xffffffffu, s,  1, 4);
        sq += __shfl_down_sync(0xffffffffu, sq, 2, 4);
        sq += __shfl_down_sync(0xffffffffu, sq, 1, 4);
        s  = __shfl_sync(0xffffffffu, s,  0, 4);
        sq = __shfl_sync(0xffffffffu, sq, 0, 4);

        const float mu  = s * (1.f / 128.f);
        const float var = sq * (1.f / 128.f) - mu * mu;
        const float inv = rsqrtf(var + 1e-5f);

#pragma unroll
        for (int u = 0; u < 8; u++) {
            int d = q * 32 + 4 * u;
            float4 gv = *(const float4*)&gamma[d];
            float4 bv = *(const float4*)&beta[d];
            float4 o;
            o.x = (pn[4 * u + 0] - mu) * inv * gv.x + bv.x;
            o.y = (pn[4 * u + 1] - mu) * inv * gv.y + bv.y;
            o.z = (pn[4 * u + 2] - mu) * inv * gv.z + bv.z;
            o.w = (pn[4 * u + 3] - mu) * inv * gv.w + bv.w;
            *(float4*)&out[(size_t)pair * D + d] = o;
        }
    }
#undef F_LOAD
}
#undef FAS
#undef FBS
#undef FCS

// ---------------------------------------------------------------------------
extern "C" void kernel_launch(void* const* d_in, const int* in_sizes, int n_in,
                              void* d_out, int out_size) {
    const float* P     = (const float*)d_in[0];
    const float* mask  = (const float*)d_in[1];
    const float* Wl    = (const float*)d_in[2];
    const float* Wr    = (const float*)d_in[3];
    const float* Wo    = (const float*)d_in[4];
    const float* gamma = (const float*)d_in[5];
    const float* beta  = (const float*)d_in[6];
    float* out = (float*)d_out;

    k_wt<<<64, 256>>>(Wo);
    k_proj<<<dim3(LL / 128, 2), 256>>>(P, mask, Wl, Wr);
    k_tri<<<dim3(L / 128, L / 128, H), 256>>>();
    k_fin<<<LL / 64, 128>>>(P, mask, gamma, beta, out);
}

// round 11
// speedup vs baseline: 1.7621x; 1.0349x over previous
#include <cuda_runtime.h>
#include <cuda_fp16.h>
#include <cstdint>

#define L  384
#define D  128
#define H  128
#define LL (L * L)   // 147456

// Scratch — static device globals (no cudaMalloc allowed).
__device__ __half g_LhT[(size_t)H * LL];  // [h][i*L+k]  (fp16)
__device__ __half g_RhT[(size_t)H * LL];  // [h][j*L+k]  (fp16, j-major)
__device__ __half g_updT[(size_t)H * LL]; // [h][i*L+j]  (fp16)
__device__ __half g_Wo2h[D * H];          // [d][h] = fp16(W_out[d][h])

// ---------------------------------------------------------------------------
// helpers
// ---------------------------------------------------------------------------
__device__ __forceinline__ unsigned f2tf(float x) {
    unsigned r; asm("cvt.rna.tf32.f32 %0, %1;" : "=r"(r) : "f"(x)); return r;
}
__device__ __forceinline__ float f2tff(float x) { return __uint_as_float(f2tf(x)); }

__device__ __forceinline__ void mma8(float c[4], const unsigned a[4], const unsigned b[2]) {
    asm volatile(
        "mma.sync.aligned.m16n8k8.row.col.f32.tf32.tf32.f32 "
        "{%0,%1,%2,%3}, {%4,%5,%6,%7}, {%8,%9}, {%0,%1,%2,%3};"
        : "+f"(c[0]), "+f"(c[1]), "+f"(c[2]), "+f"(c[3])
        : "r"(a[0]), "r"(a[1]), "r"(a[2]), "r"(a[3]), "r"(b[0]), "r"(b[1]));
}

// fp16 mma, fp32 accumulate
__device__ __forceinline__ void mma16(float c[4], const unsigned a[4], const unsigned b[2]) {
    asm volatile(
        "mma.sync.aligned.m16n8k16.row.col.f32.f16.f16.f32 "
        "{%0,%1,%2,%3}, {%4,%5,%6,%7}, {%8,%9}, {%0,%1,%2,%3};"
        : "+f"(c[0]), "+f"(c[1]), "+f"(c[2]), "+f"(c[3])
        : "r"(a[0]), "r"(a[1]), "r"(a[2]), "r"(a[3]), "r"(b[0]), "r"(b[1]));
}

__device__ __forceinline__ void ldsm4h(unsigned r[4], const __half* p) {
    unsigned a = (unsigned)__cvta_generic_to_shared(p);
    asm volatile("ldmatrix.sync.aligned.m8n8.x4.shared.b16 {%0,%1,%2,%3}, [%4];"
                 : "=r"(r[0]), "=r"(r[1]), "=r"(r[2]), "=r"(r[3]) : "r"(a));
}
// transposed variant: stored [k][m], delivers A[m][k] fragments
__device__ __forceinline__ void ldsm4t(unsigned r[4], const __half* p) {
    unsigned a = (unsigned)__cvta_generic_to_shared(p);
    asm volatile("ldmatrix.sync.aligned.m8n8.x4.trans.shared.b16 {%0,%1,%2,%3}, [%4];"
                 : "=r"(r[0]), "=r"(r[1]), "=r"(r[2]), "=r"(r[3]) : "r"(a));
}

__device__ __forceinline__ void cpa16(void* dst, const void* src) {
    unsigned sa = (unsigned)__cvta_generic_to_shared(dst);
    asm volatile("cp.async.cg.shared.global [%0], [%1], 16;" :: "r"(sa), "l"(src));
}
__device__ __forceinline__ void cpa_commit() { asm volatile("cp.async.commit_group;"); }
__device__ __forceinline__ void cpa_wait1()  { asm volatile("cp.async.wait_group 1;"); }

// ---------------------------------------------------------------------------
// Kernel 0: fp16-round W_out (native [d][h] order) -> g_Wo2h
// ---------------------------------------------------------------------------
__global__ __launch_bounds__(256) void k_wt(const float* __restrict__ Wo) {
    int idx = blockIdx.x * 256 + threadIdx.x;   // 16384
    g_Wo2h[idx] = __float2half_rn(Wo[idx]);
}

// ---------------------------------------------------------------------------
// Kernel 1: projection GEMM (tf32 mma), fp16 output. (round-10, committed)
// ---------------------------------------------------------------------------
__global__ __launch_bounds__(256) void k_proj(
    const float* __restrict__ P, const float* __restrict__ mask,
    const float* __restrict__ Wl, const float* __restrict__ Wr)
{
    __shared__ __align__(16) float sm[8768];
#define PAS(k, m) sm[(k) * 137 + (m)]
#define PBS(k, n) sm[32 * 137 + (k) * 137 + (n)]
#define PCS(n, m) sm[(n) * 132 + (m)]
    float* mV = sm + 32 * 132 + 16;

    const int tid = threadIdx.x;
    const int wid = tid >> 5, lane = tid & 31;
    const int wm = wid & 3, wn = wid >> 2;
    const int group = lane >> 2, tid4 = lane & 3;
    const int bid = blockIdx.x;
    const bool isL = (blockIdx.y == 0);
    const float* __restrict__ W = isL ? Wl : Wr;

    int srcBase, srcStride, dmBase;
    if (isL) {
        srcBase = bid * 128;  srcStride = 1;  dmBase = bid * 128;
    } else {
        int j = bid / 3, k0p = (bid % 3) * 128;
        srcBase = k0p * L + j;  srcStride = L;  dmBase = j * L + k0p;
    }

    float acc[2][8][4];
#pragma unroll
    for (int mt = 0; mt < 2; mt++)
#pragma unroll
        for (int nt = 0; nt < 8; nt++)
#pragma unroll
            for (int v = 0; v < 4; v++) acc[mt][nt][v] = 0.f;

    const int mld = tid >> 3;
    const int kld = (tid & 7) * 4;

    float4 va[4], vb[4];
#pragma unroll
    for (int p = 0; p < 4; p++) {
        va[p] = *(const float4*)&P[(size_t)(srcBase + (size_t)(mld + p * 32) * srcStride) * D + kld];
        vb[p] = *(const float4*)&W[(mld + p * 32) * D + kld];
    }

#pragma unroll
    for (int it = 0; it < 4; it++) {
        __syncthreads();
#pragma unroll
        for (int p = 0; p < 4; p++) {
            int m = mld + p * 32;
            PAS(kld + 0, m) = f2tff(va[p].x);
            PAS(kld + 1, m) = f2tff(va[p].y);
            PAS(kld + 2, m) = f2tff(va[p].z);
            PAS(kld + 3, m) = f2tff(va[p].w);
            PBS(kld + 0, m) = f2tff(vb[p].x);
            PBS(kld + 1, m) = f2tff(vb[p].y);
            PBS(kld + 2, m) = f2tff(vb[p].z);
            PBS(kld + 3, m) = f2tff(vb[p].w);
        }
        __syncthreads();
        if (it < 3) {
            int k0 = (it + 1) * 32;
#pragma unroll
            for (int p = 0; p < 4; p++) {
                va[p] = *(const float4*)&P[(size_t)(srcBase + (size_t)(mld + p * 32) * srcStride) * D + k0 + kld];
                vb[p] = *(const float4*)&W[(mld + p * 32) * D + k0 + kld];
            }
        }
#pragma unroll
        for (int ks = 0; ks < 4; ks++) {
            int k = ks * 8;
            unsigned a[2][4], b[8][2];
#pragma unroll
            for (int mt = 0; mt < 2; mt++) {
                int r = wm * 32 + mt * 16 + group;
                a[mt][0] = __float_as_uint(PAS(k + tid4, r));
                a[mt][1] = __float_as_uint(PAS(k + tid4, r + 8));
                a[mt][2] = __float_as_uint(PAS(k + tid4 + 4, r));
                a[mt][3] = __float_as_uint(PAS(k + tid4 + 4, r + 8));
            }
#pragma unroll
            for (int nt = 0; nt < 8; nt++) {
                int c = wn * 64 + nt * 8 + group;
                b[nt][0] = __float_as_uint(PBS(k + tid4, c));
                b[nt][1] = __float_as_uint(PBS(k + tid4 + 4, c));
            }
#pragma unroll
            for (int mt = 0; mt < 2; mt++)
#pragma unroll
                for (int nt = 0; nt < 8; nt++)
                    mma8(acc[mt][nt], a[mt], b[nt]);
        }
    }

    __syncthreads();
    if (tid < 128) mV[tid] = mask[dmBase + tid];
    __half* __restrict__ dst = isL ? g_LhT : g_RhT;

#pragma unroll
    for (int nc = 0; nc < 4; nc++) {
        __syncthreads();
        if (wn == (nc >> 1)) {
#pragma unroll
            for (int nt2 = 0; nt2 < 4; nt2++) {
                int nt = (nc & 1) * 4 + nt2;
                int cc = nt2 * 8 + 2 * tid4;
#pragma unroll
                for (int mt = 0; mt < 2; mt++) {
                    int r = wm * 32 + mt * 16 + group;
                    PCS(cc,     r)     = acc[mt][nt][0];
                    PCS(cc + 1, r)     = acc[mt][nt][1];
                    PCS(cc,     r + 8) = acc[mt][nt][2];
                    PCS(cc + 1, r + 8) = acc[mt][nt][3];
                }
            }
        }
        __syncthreads();
#pragma unroll
        for (int p = 0; p < 4; p++) {
            int nr = (tid >> 5) + p * 8;
            int m  = (tid & 31) * 4;
            __half2 h0 = __floats2half2_rn(PCS(nr, m + 0) * mV[m + 0],
                                           PCS(nr, m + 1) * mV[m + 1]);
            __half2 h1 = __floats2half2_rn(PCS(nr, m + 2) * mV[m + 2],
                                           PCS(nr, m + 3) * mV[m + 3]);
            uint2 u = make_uint2(*(unsigned*)&h0, *(unsigned*)&h1);
            *(uint2*)&dst[(size_t)(nc * 32 + nr) * LL + dmBase + m] = u;
        }
    }
#undef PAS
#undef PBS
#undef PCS
}

// ---------------------------------------------------------------------------
// Kernel 2: triangle einsum — fp16 mma.m16n8k16 + ldmatrix (round-10 mainloop,
// committed). Epilogue now stores fp16.
// ---------------------------------------------------------------------------
#define T_STG 10240                   // halves per stage: A 128*40 + B 128*40
#define TCS(m, j)    smf[(m) * 132 + (j)]

__global__ __launch_bounds__(256, 2) void k_tri() {
    __shared__ __align__(16) float smf[10240];   // 40,960 B
    __half* sm = (__half*)smf;

    const int tid = threadIdx.x;
    const int wid = tid >> 5, lane = tid & 31;
    const int wm = wid & 3, wn = wid >> 2;
    const int group = lane >> 2, tid4 = lane & 3;
    const size_t hoff = (size_t)blockIdx.z * LL;
    const int i0 = blockIdx.y * 128;
    const int j0 = blockIdx.x * 128;

    const __half* __restrict__ A = g_LhT + hoff;
    const __half* __restrict__ B = g_RhT + hoff;

    int aOff[2], bOff[4];
#pragma unroll
    for (int mt = 0; mt < 2; mt++)
        aOff[mt] = (wm * 32 + mt * 16 + (lane & 7) + 8 * ((lane >> 3) & 1)) * 40
                 + 8 * (lane >> 4);
#pragma unroll
    for (int p = 0; p < 4; p++)
        bOff[p] = 5120 + (wn * 64 + p * 16 + (lane & 7) + 8 * (lane >> 4)) * 40
                + 8 * ((lane >> 3) & 1);

    float acc[2][8][4];
#pragma unroll
    for (int mt = 0; mt < 2; mt++)
#pragma unroll
        for (int nt = 0; nt < 8; nt++)
#pragma unroll
            for (int v = 0; v < 4; v++) acc[mt][nt][v] = 0.f;

#define T_LOAD(s, k0)                                                              \
    {                                                                              \
        _Pragma("unroll")                                                          \
        for (int p = 0; p < 2; p++) {                                              \
            int task = tid + p * 256;                                              \
            int r = task >> 2, q = task & 3;                                       \
            cpa16(&sm[(s) * T_STG + r * 40 + q * 8],                               \
                  &A[(size_t)(i0 + r) * L + (k0) + q * 8]);                        \
            cpa16(&sm[(s) * T_STG + 5120 + r * 40 + q * 8],                        \
                  &B[(size_t)(j0 + r) * L + (k0) + q * 8]);                        \
        }                                                                          \
    }

    T_LOAD(0, 0);  cpa_commit();
    T_LOAD(1, 32); cpa_commit();

#pragma unroll 2
    for (int it = 0; it < 12; it++) {
        const int s = it & 1;
        cpa_wait1();
        __syncthreads();
#pragma unroll
        for (int ks = 0; ks < 2; ks++) {
            const int k = ks * 16;
            unsigned a[2][4], b[4][4];
#pragma unroll
            for (int mt = 0; mt < 2; mt++)
                ldsm4h(a[mt], &sm[s * T_STG + aOff[mt] + k]);
#pragma unroll
            for (int p = 0; p < 4; p++)
                ldsm4h(b[p], &sm[s * T_STG + bOff[p] + k]);
#pragma unroll
            for (int mt = 0; mt < 2; mt++)
#pragma unroll
                for (int p = 0; p < 4; p++) {
                    mma16(acc[mt][2 * p],     a[mt], &b[p][0]);
                    mma16(acc[mt][2 * p + 1], a[mt], &b[p][2]);
                }
        }
        __syncthreads();
        if (it + 2 < 12) T_LOAD(s, (it + 2) * 32);
        cpa_commit();
    }
#undef T_LOAD

    // Epilogue: two 64-row chunks staged through smem, coalesced fp16 store.
#pragma unroll 1
    for (int mc = 0; mc < 2; mc++) {
        __syncthreads();
        if ((wm >> 1) == mc) {
#pragma unroll
            for (int nt = 0; nt < 8; nt++) {
                int cc = wn * 64 + nt * 8 + 2 * tid4;
#pragma unroll
                for (int mt = 0; mt < 2; mt++) {
                    int r = (wm & 1) * 32 + mt * 16 + group;
                    TCS(r,     cc)     = acc[mt][nt][0];
                    TCS(r,     cc + 1) = acc[mt][nt][1];
                    TCS(r + 8, cc)     = acc[mt][nt][2];
                    TCS(r + 8, cc + 1) = acc[mt][nt][3];
                }
            }
        }
        __syncthreads();
#pragma unroll
        for (int p = 0; p < 8; p++) {
            int row = (tid >> 5) + p * 8;
            int j   = (tid & 31) * 4;
            __half2 h0 = __floats2half2_rn(TCS(row, j + 0), TCS(row, j + 1));
            __half2 h1 = __floats2half2_rn(TCS(row, j + 2), TCS(row, j + 3));
            uint2 u = make_uint2(*(unsigned*)&h0, *(unsigned*)&h1);
            *(uint2*)&g_updT[hoff + (size_t)(i0 + mc * 64 + row) * L + j0 + j] = u;
        }
    }
#undef TCS
}

// ---------------------------------------------------------------------------
// Kernel 3: output projection (fp16 mma.m16n8k16) + residual + mask + LN.
// A = updT^T stored [k=h][m=pair] fp16, pitch 72 halves -> ldmatrix.x4.trans.
// B = Wo2h [n=d][k=h] fp16, pitch 24 halves -> ldmatrix.x4 (verified mapping).
// 4-warp CTAs (2x2 warp grid of 32x64 tiles), BK=16, 2-stage cp.async.
// ---------------------------------------------------------------------------
#define F_STG 4224                    // halves per stage: A 16*72 + B 128*24
#define FCS(m, d)    sm[(m) * 132 + (d)]

__global__ __launch_bounds__(128, 4) void k_fin(
    const float* __restrict__ P, const float* __restrict__ mask,
    const float* __restrict__ gamma, const float* __restrict__ beta,
    float* __restrict__ out)
{
    __shared__ __align__(16) float sm[8448];   // 33,792 B (stages alias floats)
    __half* smh = (__half*)sm;

    const int tid = threadIdx.x;
    const int wid = tid >> 5, lane = tid & 31;
    const int wm = wid & 1, wn = wid >> 1;
    const int group = lane >> 2, tid4 = lane & 3;
    const int pairBase = blockIdx.x * 64;

    // A (trans): lanes 8q..8q+7 address stored k-rows of matrix q.
    int aOff[2], bOff[4];
#pragma unroll
    for (int mt = 0; mt < 2; mt++)
        aOff[mt] = ((lane & 7) + 8 * (lane >> 4)) * 72
                 + wm * 32 + mt * 16 + 8 * ((lane >> 3) & 1);
#pragma unroll
    for (int p = 0; p < 4; p++)
        bOff[p] = 1152 + (wn * 64 + p * 16 + (lane & 7) + 8 * (lane >> 4)) * 24
                + 8 * ((lane >> 3) & 1);

    float acc[2][8][4];
#pragma unroll
    for (int mt = 0; mt < 2; mt++)
#pragma unroll
        for (int nt = 0; nt < 8; nt++)
#pragma unroll
            for (int v = 0; v < 4; v++) acc[mt][nt][v] = 0.f;

#define F_LOAD(s, k0)                                                                \
    {                                                                                \
        {   /* A: 16 rows x 64 halves = 128 chunks, 1 per thread */                  \
            int k = tid >> 3, m8 = (tid & 7) * 8;                                    \
            cpa16(&smh[(s) * F_STG + k * 72 + m8],                                   \
                  &g_updT[(size_t)((k0) + k) * LL + pairBase + m8]);                 \
        }                                                                            \
        _Pragma("unroll")                                                            \
        for (int p = 0; p < 2; p++) {   /* B: 128 rows x 16 halves = 256 chunks */   \
            int task = tid + p * 128;                                                \
            int n = task >> 1, q = (task & 1) * 8;                                   \
            cpa16(&smh[(s) * F_STG + 1152 + n * 24 + q],                             \
                  &g_Wo2h[n * H + (k0) + q]);                                        \
        }                                                                            \
    }

    F_LOAD(0, 0);  cpa_commit();
    F_LOAD(1, 16); cpa_commit();

#pragma unroll 1
    for (int it = 0; it < 8; it++) {
        const int s = it & 1;
        cpa_wait1();
        __syncthreads();
        unsigned a[2][4], b[4][4];
#pragma unroll
        for (int mt = 0; mt < 2; mt++)
            ldsm4t(a[mt], &smh[s * F_STG + aOff[mt]]);
#pragma unroll
        for (int p = 0; p < 4; p++)
            ldsm4h(b[p], &smh[s * F_STG + bOff[p]]);
#pragma unroll
        for (int mt = 0; mt < 2; mt++)
#pragma unroll
            for (int p = 0; p < 4; p++) {
                mma16(acc[mt][2 * p],     a[mt], &b[p][0]);
                mma16(acc[mt][2 * p + 1], a[mt], &b[p][2]);
            }
        __syncthreads();
        if (it + 2 < 8) F_LOAD(s, (it + 2) * 16);
        cpa_commit();
    }

    // Epilogue: stage whole 64x128 acc tile -> smem, then LayerNorm.
    __syncthreads();
#pragma unroll
    for (int nt = 0; nt < 8; nt++) {
        int cc = wn * 64 + nt * 8 + 2 * tid4;
#pragma unroll
        for (int mt = 0; mt < 2; mt++) {
            int r = wm * 32 + mt * 16 + group;
            FCS(r,     cc)     = acc[mt][nt][0];
            FCS(r,     cc + 1) = acc[mt][nt][1];
            FCS(r + 8, cc)     = acc[mt][nt][2];
            FCS(r + 8, cc + 1) = acc[mt][nt][3];
        }
    }
    __syncthreads();

    // LayerNorm: 4 threads per pair-row (32 d each), two passes of 32 rows.
#pragma unroll 1
    for (int h2 = 0; h2 < 2; h2++) {
        const int row = (tid >> 2) + h2 * 32;
        const int q   = tid & 3;
        const int pair = pairBase + row;
        const float mk = mask[pair];

        float pn[32];
        float s = 0.f, sq = 0.f;
#pragma unroll
        for (int u = 0; u < 8; u++) {
            float4 pv = *(const float4*)&P[(size_t)pair * D + q * 32 + 4 * u];
            pn[4 * u + 0] = pv.x + mk * FCS(row, q * 32 + 4 * u + 0);
            pn[4 * u + 1] = pv.y + mk * FCS(row, q * 32 + 4 * u + 1);
            pn[4 * u + 2] = pv.z + mk * FCS(row, q * 32 + 4 * u + 2);
            pn[4 * u + 3] = pv.w + mk * FCS(row, q * 32 + 4 * u + 3);
        }
#pragma unroll
        for (int v = 0; v < 32; v++) { s += pn[v]; sq = fmaf(pn[v], pn[v], sq); }
        s  += __shfl_down_sync(0xffffffffu, s,  2, 4);
        s  += __shfl_down_sync(0xffffffffu, s,  1, 4);
        sq += __shfl_down_sync(0xffffffffu, sq, 2, 4);
        sq += __shfl_down_sync(0xffffffffu, sq, 1, 4);
        s  = __shfl_sync(0xffffffffu, s,  0, 4);
        sq = __shfl_sync(0xffffffffu, sq, 0, 4);

        const float mu  = s * (1.f / 128.f);
        const float var = sq * (1.f / 128.f) - mu * mu;
        const float inv = rsqrtf(var + 1e-5f);

#pragma unroll
        for (int u = 0; u < 8; u++) {
            int d = q * 32 + 4 * u;
            float4 gv = *(const float4*)&gamma[d];
            float4 bv = *(const float4*)&beta[d];
            float4 o;
            o.x = (pn[4 * u + 0] - mu) * inv * gv.x + bv.x;
            o.y = (pn[4 * u + 1] - mu) * inv * gv.y + bv.y;
            o.z = (pn[4 * u + 2] - mu) * inv * gv.z + bv.z;
            o.w = (pn[4 * u + 3] - mu) * inv * gv.w + bv.w;
            *(float4*)&out[(size_t)pair * D + d] = o;
        }
    }
#undef F_LOAD
}
#undef FCS

// ---------------------------------------------------------------------------
extern "C" void kernel_launch(void* const* d_in, const int* in_sizes, int n_in,
                              void* d_out, int out_size) {
    const float* P     = (const float*)d_in[0];
    const float* mask  = (const float*)d_in[1];
    const float* Wl    = (const float*)d_in[2];
    const float* Wr    = (const float*)d_in[3];
    const float* Wo    = (const float*)d_in[4];
    const float* gamma = (const float*)d_in[5];
    const float* beta  = (const float*)d_in[6];
    float* out = (float*)d_out;

    k_wt<<<64, 256>>>(Wo);
    k_proj<<<dim3(LL / 128, 2), 256>>>(P, mask, Wl, Wr);
    k_tri<<<dim3(L / 128, L / 128, H), 256>>>();
    k_fin<<<LL / 64, 128>>>(P, mask, gamma, beta, out);
}

// round 12
// speedup vs baseline: 1.8945x; 1.0751x over previous
#include <cuda_runtime.h>
#include <cuda_fp16.h>
#include <cstdint>

#define L  384
#define D  128
#define H  128
#define LL (L * L)   // 147456

// Scratch — static device globals (no cudaMalloc allowed).
__device__ __half g_LhT[(size_t)H * LL];  // [h][i*L+k]  (fp16)
__device__ __half g_RhT[(size_t)H * LL];  // [h][j*L+k]  (fp16, j-major)
__device__ __half g_updT[(size_t)H * LL]; // [h][i*L+j]  (fp16)
__device__ __half g_Wo2h[D * H];          // [d][h] = fp16(W_out[d][h])

// ---------------------------------------------------------------------------
// helpers
// ---------------------------------------------------------------------------
// fp16 mma, fp32 accumulate
__device__ __forceinline__ void mma16(float c[4], const unsigned a[4], const unsigned b[2]) {
    asm volatile(
        "mma.sync.aligned.m16n8k16.row.col.f32.f16.f16.f32 "
        "{%0,%1,%2,%3}, {%4,%5,%6,%7}, {%8,%9}, {%0,%1,%2,%3};"
        : "+f"(c[0]), "+f"(c[1]), "+f"(c[2]), "+f"(c[3])
        : "r"(a[0]), "r"(a[1]), "r"(a[2]), "r"(a[3]), "r"(b[0]), "r"(b[1]));
}

__device__ __forceinline__ void ldsm4h(unsigned r[4], const __half* p) {
    unsigned a = (unsigned)__cvta_generic_to_shared(p);
    asm volatile("ldmatrix.sync.aligned.m8n8.x4.shared.b16 {%0,%1,%2,%3}, [%4];"
                 : "=r"(r[0]), "=r"(r[1]), "=r"(r[2]), "=r"(r[3]) : "r"(a));
}
// transposed variant: stored [k][m], delivers A[m][k] fragments
__device__ __forceinline__ void ldsm4t(unsigned r[4], const __half* p) {
    unsigned a = (unsigned)__cvta_generic_to_shared(p);
    asm volatile("ldmatrix.sync.aligned.m8n8.x4.trans.shared.b16 {%0,%1,%2,%3}, [%4];"
                 : "=r"(r[0]), "=r"(r[1]), "=r"(r[2]), "=r"(r[3]) : "r"(a));
}

__device__ __forceinline__ void cpa16(void* dst, const void* src) {
    unsigned sa = (unsigned)__cvta_generic_to_shared(dst);
    asm volatile("cp.async.cg.shared.global [%0], [%1], 16;" :: "r"(sa), "l"(src));
}
__device__ __forceinline__ void cpa_commit() { asm volatile("cp.async.commit_group;"); }
__device__ __forceinline__ void cpa_wait1()  { asm volatile("cp.async.wait_group 1;"); }

// ---------------------------------------------------------------------------
// Kernel 0: fp16-round W_out (native [d][h] order) -> g_Wo2h
// ---------------------------------------------------------------------------
__global__ __launch_bounds__(256) void k_wt(const float* __restrict__ Wo) {
    int idx = blockIdx.x * 256 + threadIdx.x;   // 16384
    g_Wo2h[idx] = __float2half_rn(Wo[idx]);
}

// ---------------------------------------------------------------------------
// Kernel 1: projection GEMM — now fp16 mma.m16n8k16 + ldmatrix (k_tri recipe).
//   isL: Lh(i, k=c, h) masked by mask[i*L+c]  -> g_LhT[h][i*L+c]
//   isR: Rh(k, j, h)   masked by mask[j*L+k]  -> g_RhT[h][j*L+k]  (j-major)
// Block 128 rows x 128 h, BK=32, 4 iters. fp32 gmem reads converted to fp16
// at smem store. Tiles [m][32]/[n][32] halves, pitch 40 (verified layout).
// ---------------------------------------------------------------------------
#define P_STG 10240                    // halves: A 128*40 + B 128*40 (one buffer)
#define PCS(n, m) smf[(n) * 132 + (m)]

__global__ __launch_bounds__(256) void k_proj(
    const float* __restrict__ P, const float* __restrict__ mask,
    const float* __restrict__ Wl, const float* __restrict__ Wr)
{
    __shared__ __align__(16) float smf[5120];   // 20,480 B (halves alias floats)
    __half* sm = (__half*)smf;
    float* mV = smf + 32 * 132 + 16;            // 128 mask vals (epilogue reuse)

    const int tid = threadIdx.x;
    const int wid = tid >> 5, lane = tid & 31;
    const int wm = wid & 3, wn = wid >> 2;
    const int group = lane >> 2, tid4 = lane & 3;
    const int bid = blockIdx.x;
    const bool isL = (blockIdx.y == 0);
    const float* __restrict__ W = isL ? Wl : Wr;

    int srcBase, srcStride, dmBase;
    if (isL) {
        srcBase = bid * 128;  srcStride = 1;  dmBase = bid * 128;
    } else {
        int j = bid / 3, k0p = (bid % 3) * 128;
        srcBase = k0p * L + j;  srcStride = L;  dmBase = j * L + k0p;
    }

    // LDSM fragment offsets (halves) — byte-identical to k_tri's verified map.
    int aOff[2], bOff[4];
#pragma unroll
    for (int mt = 0; mt < 2; mt++)
        aOff[mt] = (wm * 32 + mt * 16 + (lane & 7) + 8 * ((lane >> 3) & 1)) * 40
                 + 8 * (lane >> 4);
#pragma unroll
    for (int p = 0; p < 4; p++)
        bOff[p] = 5120 + (wn * 64 + p * 16 + (lane & 7) + 8 * (lane >> 4)) * 40
                + 8 * ((lane >> 3) & 1);

    float acc[2][8][4];
#pragma unroll
    for (int mt = 0; mt < 2; mt++)
#pragma unroll
        for (int nt = 0; nt < 8; nt++)
#pragma unroll
            for (int v = 0; v < 4; v++) acc[mt][nt][v] = 0.f;

    const int mld = tid >> 3;          // 0..31 (+32p)
    const int kld = (tid & 7) * 4;     // 0..28

    float4 va[4], vb[4];
#define P_FETCH(k0)                                                                 \
    {                                                                               \
        _Pragma("unroll")                                                           \
        for (int p = 0; p < 4; p++) {                                               \
            int m = mld + p * 32;                                                   \
            va[p] = *(const float4*)&P[(size_t)(srcBase + (size_t)m * srcStride) * D + (k0) + kld]; \
            vb[p] = *(const float4*)&W[m * D + (k0) + kld];                         \
        }                                                                           \
    }
#define P_STORE()                                                                   \
    {                                                                               \
        _Pragma("unroll")                                                           \
        for (int p = 0; p < 4; p++) {                                               \
            int m = mld + p * 32;                                                   \
            __half2 a0 = __floats2half2_rn(va[p].x, va[p].y);                       \
            __half2 a1 = __floats2half2_rn(va[p].z, va[p].w);                       \
            __half2 b0 = __floats2half2_rn(vb[p].x, vb[p].y);                       \
            __half2 b1 = __floats2half2_rn(vb[p].z, vb[p].w);                       \
            *(unsigned*)&sm[m * 40 + kld]            = *(unsigned*)&a0;             \
            *(unsigned*)&sm[m * 40 + kld + 2]        = *(unsigned*)&a1;             \
            *(unsigned*)&sm[5120 + m * 40 + kld]     = *(unsigned*)&b0;             \
            *(unsigned*)&sm[5120 + m * 40 + kld + 2] = *(unsigned*)&b1;             \
        }                                                                           \
    }

    P_FETCH(0);

#pragma unroll 1
    for (int it = 0; it < 4; it++) {
        __syncthreads();
        P_STORE();
        __syncthreads();
        if (it < 3) P_FETCH((it + 1) * 32);
#pragma unroll
        for (int ks = 0; ks < 2; ks++) {
            const int k = ks * 16;
            unsigned a[2][4], b[4][4];
#pragma unroll
            for (int mt = 0; mt < 2; mt++)
                ldsm4h(a[mt], &sm[aOff[mt] + k]);
#pragma unroll
            for (int p = 0; p < 4; p++)
                ldsm4h(b[p], &sm[bOff[p] + k]);
#pragma unroll
            for (int mt = 0; mt < 2; mt++)
#pragma unroll
                for (int p = 0; p < 4; p++) {
                    mma16(acc[mt][2 * p],     a[mt], &b[p][0]);
                    mma16(acc[mt][2 * p + 1], a[mt], &b[p][2]);
                }
        }
    }
#undef P_FETCH
#undef P_STORE

    __syncthreads();
    if (tid < 128) mV[tid] = mask[dmBase + tid];
    __half* __restrict__ dst = isL ? g_LhT : g_RhT;

#pragma unroll 1
    for (int nc = 0; nc < 4; nc++) {
        __syncthreads();
        if (wn == (nc >> 1)) {
#pragma unroll
            for (int nt2 = 0; nt2 < 4; nt2++) {
                int nt = (nc & 1) * 4 + nt2;
                int cc = nt2 * 8 + 2 * tid4;
#pragma unroll
                for (int mt = 0; mt < 2; mt++) {
                    int r = wm * 32 + mt * 16 + group;
                    PCS(cc,     r)     = acc[mt][nt][0];
                    PCS(cc + 1, r)     = acc[mt][nt][1];
                    PCS(cc,     r + 8) = acc[mt][nt][2];
                    PCS(cc + 1, r + 8) = acc[mt][nt][3];
                }
            }
        }
        __syncthreads();
#pragma unroll
        for (int p = 0; p < 4; p++) {
            int nr = (tid >> 5) + p * 8;
            int m  = (tid & 31) * 4;
            __half2 h0 = __floats2half2_rn(PCS(nr, m + 0) * mV[m + 0],
                                           PCS(nr, m + 1) * mV[m + 1]);
            __half2 h1 = __floats2half2_rn(PCS(nr, m + 2) * mV[m + 2],
                                           PCS(nr, m + 3) * mV[m + 3]);
            uint2 u = make_uint2(*(unsigned*)&h0, *(unsigned*)&h1);
            *(uint2*)&dst[(size_t)(nc * 32 + nr) * LL + dmBase + m] = u;
        }
    }
#undef PCS
}

// ---------------------------------------------------------------------------
// Kernel 2: triangle einsum — fp16 mma.m16n8k16 + ldmatrix (committed).
// ---------------------------------------------------------------------------
#define T_STG 10240                   // halves per stage: A 128*40 + B 128*40
#define TCS(m, j)    smf[(m) * 132 + (j)]

__global__ __launch_bounds__(256, 2) void k_tri() {
    __shared__ __align__(16) float smf[10240];   // 40,960 B
    __half* sm = (__half*)smf;

    const int tid = threadIdx.x;
    const int wid = tid >> 5, lane = tid & 31;
    const int wm = wid & 3, wn = wid >> 2;
    const int group = lane >> 2, tid4 = lane & 3;
    const size_t hoff = (size_t)blockIdx.z * LL;
    const int i0 = blockIdx.y * 128;
    const int j0 = blockIdx.x * 128;

    const __half* __restrict__ A = g_LhT + hoff;
    const __half* __restrict__ B = g_RhT + hoff;

    int aOff[2], bOff[4];
#pragma unroll
    for (int mt = 0; mt < 2; mt++)
        aOff[mt] = (wm * 32 + mt * 16 + (lane & 7) + 8 * ((lane >> 3) & 1)) * 40
                 + 8 * (lane >> 4);
#pragma unroll
    for (int p = 0; p < 4; p++)
        bOff[p] = 5120 + (wn * 64 + p * 16 + (lane & 7) + 8 * (lane >> 4)) * 40
                + 8 * ((lane >> 3) & 1);

    float acc[2][8][4];
#pragma unroll
    for (int mt = 0; mt < 2; mt++)
#pragma unroll
        for (int nt = 0; nt < 8; nt++)
#pragma unroll
            for (int v = 0; v < 4; v++) acc[mt][nt][v] = 0.f;

#define T_LOAD(s, k0)                                                              \
    {                                                                              \
        _Pragma("unroll")                                                          \
        for (int p = 0; p < 2; p++) {                                              \
            int task = tid + p * 256;                                              \
            int r = task >> 2, q = task & 3;                                       \
            cpa16(&sm[(s) * T_STG + r * 40 + q * 8],                               \
                  &A[(size_t)(i0 + r) * L + (k0) + q * 8]);                        \
            cpa16(&sm[(s) * T_STG + 5120 + r * 40 + q * 8],                        \
                  &B[(size_t)(j0 + r) * L + (k0) + q * 8]);                        \
        }                                                                          \
    }

    T_LOAD(0, 0);  cpa_commit();
    T_LOAD(1, 32); cpa_commit();

#pragma unroll 2
    for (int it = 0; it < 12; it++) {
        const int s = it & 1;
        cpa_wait1();
        __syncthreads();
#pragma unroll
        for (int ks = 0; ks < 2; ks++) {
            const int k = ks * 16;
            unsigned a[2][4], b[4][4];
#pragma unroll
            for (int mt = 0; mt < 2; mt++)
                ldsm4h(a[mt], &sm[s * T_STG + aOff[mt] + k]);
#pragma unroll
            for (int p = 0; p < 4; p++)
                ldsm4h(b[p], &sm[s * T_STG + bOff[p] + k]);
#pragma unroll
            for (int mt = 0; mt < 2; mt++)
#pragma unroll
                for (int p = 0; p < 4; p++) {
                    mma16(acc[mt][2 * p],     a[mt], &b[p][0]);
                    mma16(acc[mt][2 * p + 1], a[mt], &b[p][2]);
                }
        }
        __syncthreads();
        if (it + 2 < 12) T_LOAD(s, (it + 2) * 32);
        cpa_commit();
    }
#undef T_LOAD

    // Epilogue: two 64-row chunks staged through smem, coalesced fp16 store.
#pragma unroll 1
    for (int mc = 0; mc < 2; mc++) {
        __syncthreads();
        if ((wm >> 1) == mc) {
#pragma unroll
            for (int nt = 0; nt < 8; nt++) {
                int cc = wn * 64 + nt * 8 + 2 * tid4;
#pragma unroll
                for (int mt = 0; mt < 2; mt++) {
                    int r = (wm & 1) * 32 + mt * 16 + group;
                    TCS(r,     cc)     = acc[mt][nt][0];
                    TCS(r,     cc + 1) = acc[mt][nt][1];
                    TCS(r + 8, cc)     = acc[mt][nt][2];
                    TCS(r + 8, cc + 1) = acc[mt][nt][3];
                }
            }
        }
        __syncthreads();
#pragma unroll
        for (int p = 0; p < 8; p++) {
            int row = (tid >> 5) + p * 8;
            int j   = (tid & 31) * 4;
            __half2 h0 = __floats2half2_rn(TCS(row, j + 0), TCS(row, j + 1));
            __half2 h1 = __floats2half2_rn(TCS(row, j + 2), TCS(row, j + 3));
            uint2 u = make_uint2(*(unsigned*)&h0, *(unsigned*)&h1);
            *(uint2*)&g_updT[hoff + (size_t)(i0 + mc * 64 + row) * L + j0 + j] = u;
        }
    }
#undef TCS
}

// ---------------------------------------------------------------------------
// Kernel 3: output projection (fp16 mma) + residual + mask + LN (committed).
// ---------------------------------------------------------------------------
#define F_STG 4224                    // halves per stage: A 16*72 + B 128*24
#define FCS(m, d)    sm[(m) * 132 + (d)]

__global__ __launch_bounds__(128, 4) void k_fin(
    const float* __restrict__ P, const float* __restrict__ mask,
    const float* __restrict__ gamma, const float* __restrict__ beta,
    float* __restrict__ out)
{
    __shared__ __align__(16) float sm[8448];
    __half* smh = (__half*)sm;

    const int tid = threadIdx.x;
    const int wid = tid >> 5, lane = tid & 31;
    const int wm = wid & 1, wn = wid >> 1;
    const int group = lane >> 2, tid4 = lane & 3;
    const int pairBase = blockIdx.x * 64;

    int aOff[2], bOff[4];
#pragma unroll
    for (int mt = 0; mt < 2; mt++)
        aOff[mt] = ((lane & 7) + 8 * (lane >> 4)) * 72
                 + wm * 32 + mt * 16 + 8 * ((lane >> 3) & 1);
#pragma unroll
    for (int p = 0; p < 4; p++)
        bOff[p] = 1152 + (wn * 64 + p * 16 + (lane & 7) + 8 * (lane >> 4)) * 24
                + 8 * ((lane >> 3) & 1);

    float acc[2][8][4];
#pragma unroll
    for (int mt = 0; mt < 2; mt++)
#pragma unroll
        for (int nt = 0; nt < 8; nt++)
#pragma unroll
            for (int v = 0; v < 4; v++) acc[mt][nt][v] = 0.f;

#define F_LOAD(s, k0)                                                                \
    {                                                                                \
        {                                                                            \
            int k = tid >> 3, m8 = (tid & 7) * 8;                                    \
            cpa16(&smh[(s) * F_STG + k * 72 + m8],                                   \
                  &g_updT[(size_t)((k0) + k) * LL + pairBase + m8]);                 \
        }                                                                            \
        _Pragma("unroll")                                                            \
        for (int p = 0; p < 2; p++) {                                                \
            int task = tid + p * 128;                                                \
            int n = task >> 1, q = (task & 1) * 8;                                   \
            cpa16(&smh[(s) * F_STG + 1152 + n * 24 + q],                             \
                  &g_Wo2h[n * H + (k0) + q]);                                        \
        }                                                                            \
    }

    F_LOAD(0, 0);  cpa_commit();
    F_LOAD(1, 16); cpa_commit();

#pragma unroll 1
    for (int it = 0; it < 8; it++) {
        const int s = it & 1;
        cpa_wait1();
        __syncthreads();
        unsigned a[2][4], b[4][4];
#pragma unroll
        for (int mt = 0; mt < 2; mt++)
            ldsm4t(a[mt], &smh[s * F_STG + aOff[mt]]);
#pragma unroll
        for (int p = 0; p < 4; p++)
            ldsm4h(b[p], &smh[s * F_STG + bOff[p]]);
#pragma unroll
        for (int mt = 0; mt < 2; mt++)
#pragma unroll
            for (int p = 0; p < 4; p++) {
                mma16(acc[mt][2 * p],     a[mt], &b[p][0]);
                mma16(acc[mt][2 * p + 1], a[mt], &b[p][2]);
            }
        __syncthreads();
        if (it + 2 < 8) F_LOAD(s, (it + 2) * 16);
        cpa_commit();
    }

    __syncthreads();
#pragma unroll
    for (int nt = 0; nt < 8; nt++) {
        int cc = wn * 64 + nt * 8 + 2 * tid4;
#pragma unroll
        for (int mt = 0; mt < 2; mt++) {
            int r = wm * 32 + mt * 16 + group;
            FCS(r,     cc)     = acc[mt][nt][0];
            FCS(r,     cc + 1) = acc[mt][nt][1];
            FCS(r + 8, cc)     = acc[mt][nt][2];
            FCS(r + 8, cc + 1) = acc[mt][nt][3];
        }
    }
    __syncthreads();

#pragma unroll 1
    for (int h2 = 0; h2 < 2; h2++) {
        const int row = (tid >> 2) + h2 * 32;
        const int q   = tid & 3;
        const int pair = pairBase + row;
        const float mk = mask[pair];

        float pn[32];
        float s = 0.f, sq = 0.f;
#pragma unroll
        for (int u = 0; u < 8; u++) {
            float4 pv = *(const float4*)&P[(size_t)pair * D + q * 32 + 4 * u];
            pn[4 * u + 0] = pv.x + mk * FCS(row, q * 32 + 4 * u + 0);
            pn[4 * u + 1] = pv.y + mk * FCS(row, q * 32 + 4 * u + 1);
            pn[4 * u + 2] = pv.z + mk * FCS(row, q * 32 + 4 * u + 2);
            pn[4 * u + 3] = pv.w + mk * FCS(row, q * 32 + 4 * u + 3);
        }
#pragma unroll
        for (int v = 0; v < 32; v++) { s += pn[v]; sq = fmaf(pn[v], pn[v], sq); }
        s  += __shfl_down_sync(0xffffffffu, s,  2, 4);
        s  += __shfl_down_sync(0xffffffffu, s,  1, 4);
        sq += __shfl_down_sync(0xffffffffu, sq, 2, 4);
        sq += __shfl_down_sync(0xffffffffu, sq, 1, 4);
        s  = __shfl_sync(0xffffffffu, s,  0, 4);
        sq = __shfl_sync(0xffffffffu, sq, 0, 4);

        const float mu  = s * (1.f / 128.f);
        const float var = sq * (1.f / 128.f) - mu * mu;
        const float inv = rsqrtf(var + 1e-5f);

#pragma unroll
        for (int u = 0; u < 8; u++) {
            int d = q * 32 + 4 * u;
            float4 gv = *(const float4*)&gamma[d];
            float4 bv = *(const float4*)&beta[d];
            float4 o;
            o.x = (pn[4 * u + 0] - mu) * inv * gv.x + bv.x;
            o.y = (pn[4 * u + 1] - mu) * inv * gv.y + bv.y;
            o.z = (pn[4 * u + 2] - mu) * inv * gv.z + bv.z;
            o.w = (pn[4 * u + 3] - mu) * inv * gv.w + bv.w;
            *(float4*)&out[(size_t)pair * D + d] = o;
        }
    }
#undef F_LOAD
}
#undef FCS

// ---------------------------------------------------------------------------
extern "C" void kernel_launch(void* const* d_in, const int* in_sizes, int n_in,
                              void* d_out, int out_size) {
    const float* P     = (const float*)d_in[0];
    const float* mask  = (const float*)d_in[1];
    const float* Wl    = (const float*)d_in[2];
    const float* Wr    = (const float*)d_in[3];
    const float* Wo    = (const float*)d_in[4];
    const float* gamma = (const float*)d_in[5];
    const float* beta  = (const float*)d_in[6];
    float* out = (float*)d_out;

    k_wt<<<64, 256>>>(Wo);
    k_proj<<<dim3(LL / 128, 2), 256>>>(P, mask, Wl, Wr);
    k_tri<<<dim3(L / 128, L / 128, H), 256>>>();
    k_fin<<<LL / 64, 128>>>(P, mask, gamma, beta, out);
}

// round 13
// speedup vs baseline: 1.8969x; 1.0012x over previous
#include <cuda_runtime.h>
#include <cuda_fp16.h>
#include <cstdint>

#define L  384
#define D  128
#define H  128
#define LL (L * L)   // 147456

// Scratch — static device globals (no cudaMalloc allowed).
__device__ __half g_LhT[(size_t)H * LL];  // [h][i*L+k]  (fp16)
__device__ __half g_RhT[(size_t)H * LL];  // [h][j*L+k]  (fp16, j-major)
__device__ __half g_updT[(size_t)H * LL]; // [h][i*L+j]  (fp16)
__device__ __half g_Wo2h[D * H];          // [d][h] = fp16(W_out[d][h])

// ---------------------------------------------------------------------------
// helpers
// ---------------------------------------------------------------------------
__device__ __forceinline__ void mma16(float c[4], const unsigned a[4], const unsigned b[2]) {
    asm volatile(
        "mma.sync.aligned.m16n8k16.row.col.f32.f16.f16.f32 "
        "{%0,%1,%2,%3}, {%4,%5,%6,%7}, {%8,%9}, {%0,%1,%2,%3};"
        : "+f"(c[0]), "+f"(c[1]), "+f"(c[2]), "+f"(c[3])
        : "r"(a[0]), "r"(a[1]), "r"(a[2]), "r"(a[3]), "r"(b[0]), "r"(b[1]));
}

__device__ __forceinline__ void ldsm4h(unsigned r[4], const __half* p) {
    unsigned a = (unsigned)__cvta_generic_to_shared(p);
    asm volatile("ldmatrix.sync.aligned.m8n8.x4.shared.b16 {%0,%1,%2,%3}, [%4];"
                 : "=r"(r[0]), "=r"(r[1]), "=r"(r[2]), "=r"(r[3]) : "r"(a));
}
__device__ __forceinline__ void ldsm4t(unsigned r[4], const __half* p) {
    unsigned a = (unsigned)__cvta_generic_to_shared(p);
    asm volatile("ldmatrix.sync.aligned.m8n8.x4.trans.shared.b16 {%0,%1,%2,%3}, [%4];"
                 : "=r"(r[0]), "=r"(r[1]), "=r"(r[2]), "=r"(r[3]) : "r"(a));
}

__device__ __forceinline__ void cpa16(void* dst, const void* src) {
    unsigned sa = (unsigned)__cvta_generic_to_shared(dst);
    asm volatile("cp.async.cg.shared.global [%0], [%1], 16;" :: "r"(sa), "l"(src));
}
__device__ __forceinline__ void cpa_commit() { asm volatile("cp.async.commit_group;"); }
__device__ __forceinline__ void cpa_wait2()  { asm volatile("cp.async.wait_group 2;"); }

// ---------------------------------------------------------------------------
// Kernel 0: fp16-round W_out (native [d][h] order) -> g_Wo2h
// ---------------------------------------------------------------------------
__global__ __launch_bounds__(256) void k_wt(const float* __restrict__ Wo) {
    int idx = blockIdx.x * 256 + threadIdx.x;   // 16384
    g_Wo2h[idx] = __float2half_rn(Wo[idx]);
}

// ---------------------------------------------------------------------------
// Kernel 1: projection GEMM — fp16 mma.m16n8k16 + ldmatrix (round-12, committed).
// ---------------------------------------------------------------------------
#define PCS(n, m) smf[(n) * 132 + (m)]

__global__ __launch_bounds__(256) void k_proj(
    const float* __restrict__ P, const float* __restrict__ mask,
    const float* __restrict__ Wl, const float* __restrict__ Wr)
{
    __shared__ __align__(16) float smf[5120];   // 20,480 B (halves alias floats)
    __half* sm = (__half*)smf;
    float* mV = smf + 32 * 132 + 16;            // 128 mask vals (epilogue reuse)

    const int tid = threadIdx.x;
    const int wid = tid >> 5, lane = tid & 31;
    const int wm = wid & 3, wn = wid >> 2;
    const int group = lane >> 2, tid4 = lane & 3;
    const int bid = blockIdx.x;
    const bool isL = (blockIdx.y == 0);
    const float* __restrict__ W = isL ? Wl : Wr;

    int srcBase, srcStride, dmBase;
    if (isL) {
        srcBase = bid * 128;  srcStride = 1;  dmBase = bid * 128;
    } else {
        int j = bid / 3, k0p = (bid % 3) * 128;
        srcBase = k0p * L + j;  srcStride = L;  dmBase = j * L + k0p;
    }

    int aOff[2], bOff[4];
#pragma unroll
    for (int mt = 0; mt < 2; mt++)
        aOff[mt] = (wm * 32 + mt * 16 + (lane & 7) + 8 * ((lane >> 3) & 1)) * 40
                 + 8 * (lane >> 4);
#pragma unroll
    for (int p = 0; p < 4; p++)
        bOff[p] = 5120 + (wn * 64 + p * 16 + (lane & 7) + 8 * (lane >> 4)) * 40
                + 8 * ((lane >> 3) & 1);

    float acc[2][8][4];
#pragma unroll
    for (int mt = 0; mt < 2; mt++)
#pragma unroll
        for (int nt = 0; nt < 8; nt++)
#pragma unroll
            for (int v = 0; v < 4; v++) acc[mt][nt][v] = 0.f;

    const int mld = tid >> 3;          // 0..31 (+32p)
    const int kld = (tid & 7) * 4;     // 0..28

    float4 va[4], vb[4];
#define P_FETCH(k0)                                                                 \
    {                                                                               \
        _Pragma("unroll")                                                           \
        for (int p = 0; p < 4; p++) {                                               \
            int m = mld + p * 32;                                                   \
            va[p] = *(const float4*)&P[(size_t)(srcBase + (size_t)m * srcStride) * D + (k0) + kld]; \
            vb[p] = *(const float4*)&W[m * D + (k0) + kld];                         \
        }                                                                           \
    }
#define P_STORE()                                                                   \
    {                                                                               \
        _Pragma("unroll")                                                           \
        for (int p = 0; p < 4; p++) {                                               \
            int m = mld + p * 32;                                                   \
            __half2 a0 = __floats2half2_rn(va[p].x, va[p].y);                       \
            __half2 a1 = __floats2half2_rn(va[p].z, va[p].w);                       \
            __half2 b0 = __floats2half2_rn(vb[p].x, vb[p].y);                       \
            __half2 b1 = __floats2half2_rn(vb[p].z, vb[p].w);                       \
            *(unsigned*)&sm[m * 40 + kld]            = *(unsigned*)&a0;             \
            *(unsigned*)&sm[m * 40 + kld + 2]        = *(unsigned*)&a1;             \
            *(unsigned*)&sm[5120 + m * 40 + kld]     = *(unsigned*)&b0;             \
            *(unsigned*)&sm[5120 + m * 40 + kld + 2] = *(unsigned*)&b1;             \
        }                                                                           \
    }

    P_FETCH(0);

#pragma unroll 1
    for (int it = 0; it < 4; it++) {
        __syncthreads();
        P_STORE();
        __syncthreads();
        if (it < 3) P_FETCH((it + 1) * 32);
#pragma unroll
        for (int ks = 0; ks < 2; ks++) {
            const int k = ks * 16;
            unsigned a[2][4], b[4][4];
#pragma unroll
            for (int mt = 0; mt < 2; mt++)
                ldsm4h(a[mt], &sm[aOff[mt] + k]);
#pragma unroll
            for (int p = 0; p < 4; p++)
                ldsm4h(b[p], &sm[bOff[p] + k]);
#pragma unroll
            for (int mt = 0; mt < 2; mt++)
#pragma unroll
                for (int p = 0; p < 4; p++) {
                    mma16(acc[mt][2 * p],     a[mt], &b[p][0]);
                    mma16(acc[mt][2 * p + 1], a[mt], &b[p][2]);
                }
        }
    }
#undef P_FETCH
#undef P_STORE

    __syncthreads();
    if (tid < 128) mV[tid] = mask[dmBase + tid];
    __half* __restrict__ dst = isL ? g_LhT : g_RhT;

#pragma unroll 1
    for (int nc = 0; nc < 4; nc++) {
        __syncthreads();
        if (wn == (nc >> 1)) {
#pragma unroll
            for (int nt2 = 0; nt2 < 4; nt2++) {
                int nt = (nc & 1) * 4 + nt2;
                int cc = nt2 * 8 + 2 * tid4;
#pragma unroll
                for (int mt = 0; mt < 2; mt++) {
                    int r = wm * 32 + mt * 16 + group;
                    PCS(cc,     r)     = acc[mt][nt][0];
                    PCS(cc + 1, r)     = acc[mt][nt][1];
                    PCS(cc,     r + 8) = acc[mt][nt][2];
                    PCS(cc + 1, r + 8) = acc[mt][nt][3];
                }
            }
        }
        __syncthreads();
#pragma unroll
        for (int p = 0; p < 4; p++) {
            int nr = (tid >> 5) + p * 8;
            int m  = (tid & 31) * 4;
            __half2 h0 = __floats2half2_rn(PCS(nr, m + 0) * mV[m + 0],
                                           PCS(nr, m + 1) * mV[m + 1]);
            __half2 h1 = __floats2half2_rn(PCS(nr, m + 2) * mV[m + 2],
                                           PCS(nr, m + 3) * mV[m + 3]);
            uint2 u = make_uint2(*(unsigned*)&h0, *(unsigned*)&h1);
            *(uint2*)&dst[(size_t)(nc * 32 + nr) * LL + dmBase + m] = u;
        }
    }
#undef PCS
}

// ---------------------------------------------------------------------------
// Kernel 2: triangle einsum — fp16 mma + ldmatrix, 3-stage cp.async pipeline.
// Dynamic smem: 3 stages x 20,480 B = 61,440 B (epilogue aliases stages).
// ---------------------------------------------------------------------------
#define T_STG 10240                   // halves per stage: A 128*40 + B 128*40
#define T_SMEM (3 * T_STG * 2)        // 61,440 B
#define TCS(m, j)    smf[(m) * 132 + (j)]

__global__ __launch_bounds__(256, 2) void k_tri() {
    extern __shared__ __align__(16) float smf[];
    __half* sm = (__half*)smf;

    const int tid = threadIdx.x;
    const int wid = tid >> 5, lane = tid & 31;
    const int wm = wid & 3, wn = wid >> 2;
    const int group = lane >> 2, tid4 = lane & 3;
    const size_t hoff = (size_t)blockIdx.z * LL;
    const int i0 = blockIdx.y * 128;
    const int j0 = blockIdx.x * 128;

    const __half* __restrict__ A = g_LhT + hoff;
    const __half* __restrict__ B = g_RhT + hoff;

    int aOff[2], bOff[4];
#pragma unroll
    for (int mt = 0; mt < 2; mt++)
        aOff[mt] = (wm * 32 + mt * 16 + (lane & 7) + 8 * ((lane >> 3) & 1)) * 40
                 + 8 * (lane >> 4);
#pragma unroll
    for (int p = 0; p < 4; p++)
        bOff[p] = 5120 + (wn * 64 + p * 16 + (lane & 7) + 8 * (lane >> 4)) * 40
                + 8 * ((lane >> 3) & 1);

    float acc[2][8][4];
#pragma unroll
    for (int mt = 0; mt < 2; mt++)
#pragma unroll
        for (int nt = 0; nt < 8; nt++)
#pragma unroll
            for (int v = 0; v < 4; v++) acc[mt][nt][v] = 0.f;

#define T_LOAD(s, k0)                                                              \
    {                                                                              \
        _Pragma("unroll")                                                          \
        for (int p = 0; p < 2; p++) {                                              \
            int task = tid + p * 256;                                              \
            int r = task >> 2, q = task & 3;                                       \
            cpa16(&sm[(s) * T_STG + r * 40 + q * 8],                               \
                  &A[(size_t)(i0 + r) * L + (k0) + q * 8]);                        \
            cpa16(&sm[(s) * T_STG + 5120 + r * 40 + q * 8],                        \
                  &B[(size_t)(j0 + r) * L + (k0) + q * 8]);                        \
        }                                                                          \
    }

    T_LOAD(0, 0);  cpa_commit();
    T_LOAD(1, 32); cpa_commit();
    T_LOAD(2, 64); cpa_commit();

#pragma unroll 3
    for (int it = 0; it < 12; it++) {
        const int s = it % 3;
        cpa_wait2();
        __syncthreads();
#pragma unroll
        for (int ks = 0; ks < 2; ks++) {
            const int k = ks * 16;
            unsigned a[2][4], b[4][4];
#pragma unroll
            for (int mt = 0; mt < 2; mt++)
                ldsm4h(a[mt], &sm[s * T_STG + aOff[mt] + k]);
#pragma unroll
            for (int p = 0; p < 4; p++)
                ldsm4h(b[p], &sm[s * T_STG + bOff[p] + k]);
#pragma unroll
            for (int mt = 0; mt < 2; mt++)
#pragma unroll
                for (int p = 0; p < 4; p++) {
                    mma16(acc[mt][2 * p],     a[mt], &b[p][0]);
                    mma16(acc[mt][2 * p + 1], a[mt], &b[p][2]);
                }
        }
        __syncthreads();
        if (it + 3 < 12) T_LOAD(s, (it + 3) * 32);
        cpa_commit();
    }
#undef T_LOAD

    // Epilogue: two 64-row chunks staged through smem, coalesced fp16 store.
#pragma unroll 1
    for (int mc = 0; mc < 2; mc++) {
        __syncthreads();
        if ((wm >> 1) == mc) {
#pragma unroll
            for (int nt = 0; nt < 8; nt++) {
                int cc = wn * 64 + nt * 8 + 2 * tid4;
#pragma unroll
                for (int mt = 0; mt < 2; mt++) {
                    int r = (wm & 1) * 32 + mt * 16 + group;
                    TCS(r,     cc)     = acc[mt][nt][0];
                    TCS(r,     cc + 1) = acc[mt][nt][1];
                    TCS(r + 8, cc)     = acc[mt][nt][2];
                    TCS(r + 8, cc + 1) = acc[mt][nt][3];
                }
            }
        }
        __syncthreads();
#pragma unroll
        for (int p = 0; p < 8; p++) {
            int row = (tid >> 5) + p * 8;
            int j   = (tid & 31) * 4;
            __half2 h0 = __floats2half2_rn(TCS(row, j + 0), TCS(row, j + 1));
            __half2 h1 = __floats2half2_rn(TCS(row, j + 2), TCS(row, j + 3));
            uint2 u = make_uint2(*(unsigned*)&h0, *(unsigned*)&h1);
            *(uint2*)&g_updT[hoff + (size_t)(i0 + mc * 64 + row) * L + j0 + j] = u;
        }
    }
#undef TCS
}

// ---------------------------------------------------------------------------
// Kernel 3: output projection (fp16 mma) + residual + mask + LN.
// Now 3-stage cp.async (stages fit in existing epilogue buffer: 25.3 < 33.8 KB).
// ---------------------------------------------------------------------------
#define F_STG 4224                    // halves per stage: A 16*72 + B 128*24
#define FCS(m, d)    sm[(m) * 132 + (d)]

__global__ __launch_bounds__(128, 4) void k_fin(
    const float* __restrict__ P, const float* __restrict__ mask,
    const float* __restrict__ gamma, const float* __restrict__ beta,
    float* __restrict__ out)
{
    __shared__ __align__(16) float sm[8448];   // 33,792 B
    __half* smh = (__half*)sm;

    const int tid = threadIdx.x;
    const int wid = tid >> 5, lane = tid & 31;
    const int wm = wid & 1, wn = wid >> 1;
    const int group = lane >> 2, tid4 = lane & 3;
    const int pairBase = blockIdx.x * 64;

    int aOff[2], bOff[4];
#pragma unroll
    for (int mt = 0; mt < 2; mt++)
        aOff[mt] = ((lane & 7) + 8 * (lane >> 4)) * 72
                 + wm * 32 + mt * 16 + 8 * ((lane >> 3) & 1);
#pragma unroll
    for (int p = 0; p < 4; p++)
        bOff[p] = 1152 + (wn * 64 + p * 16 + (lane & 7) + 8 * (lane >> 4)) * 24
                + 8 * ((lane >> 3) & 1);

    float acc[2][8][4];
#pragma unroll
    for (int mt = 0; mt < 2; mt++)
#pragma unroll
        for (int nt = 0; nt < 8; nt++)
#pragma unroll
            for (int v = 0; v < 4; v++) acc[mt][nt][v] = 0.f;

#define F_LOAD(s, k0)                                                                \
    {                                                                                \
        {                                                                            \
            int k = tid >> 3, m8 = (tid & 7) * 8;                                    \
            cpa16(&smh[(s) * F_STG + k * 72 + m8],                                   \
                  &g_updT[(size_t)((k0) + k) * LL + pairBase + m8]);                 \
        }                                                                            \
        _Pragma("unroll")                                                            \
        for (int p = 0; p < 2; p++) {                                                \
            int task = tid + p * 128;                                                \
            int n = task >> 1, q = (task & 1) * 8;                                   \
            cpa16(&smh[(s) * F_STG + 1152 + n * 24 + q],                             \
                  &g_Wo2h[n * H + (k0) + q]);                                        \
        }                                                                            \
    }

    F_LOAD(0, 0);  cpa_commit();
    F_LOAD(1, 16); cpa_commit();
    F_LOAD(2, 32); cpa_commit();

#pragma unroll 1
    for (int it = 0; it < 8; it++) {
        const int s = it % 3;
        cpa_wait2();
        __syncthreads();
        unsigned a[2][4], b[4][4];
#pragma unroll
        for (int mt = 0; mt < 2; mt++)
            ldsm4t(a[mt], &smh[s * F_STG + aOff[mt]]);
#pragma unroll
        for (int p = 0; p < 4; p++)
            ldsm4h(b[p], &smh[s * F_STG + bOff[p]]);
#pragma unroll
        for (int mt = 0; mt < 2; mt++)
#pragma unroll
            for (int p = 0; p < 4; p++) {
                mma16(acc[mt][2 * p],     a[mt], &b[p][0]);
                mma16(acc[mt][2 * p + 1], a[mt], &b[p][2]);
            }
        __syncthreads();
        if (it + 3 < 8) F_LOAD(s, (it + 3) * 16);
        cpa_commit();
    }

    // Epilogue: stage whole 64x128 acc tile -> smem, then LayerNorm.
    __syncthreads();
#pragma unroll
    for (int nt = 0; nt < 8; nt++) {
        int cc = wn * 64 + nt * 8 + 2 * tid4;
#pragma unroll
        for (int mt = 0; mt < 2; mt++) {
            int r = wm * 32 + mt * 16 + group;
            FCS(r,     cc)     = acc[mt][nt][0];
            FCS(r,     cc + 1) = acc[mt][nt][1];
            FCS(r + 8, cc)     = acc[mt][nt][2];
            FCS(r + 8, cc + 1) = acc[mt][nt][3];
        }
    }
    __syncthreads();

#pragma unroll 1
    for (int h2 = 0; h2 < 2; h2++) {
        const int row = (tid >> 2) + h2 * 32;
        const int q   = tid & 3;
        const int pair = pairBase + row;
        const float mk = mask[pair];

        float pn[32];
        float s = 0.f, sq = 0.f;
#pragma unroll
        for (int u = 0; u < 8; u++) {
            float4 pv = *(const float4*)&P[(size_t)pair * D + q * 32 + 4 * u];
            pn[4 * u + 0] = pv.x + mk * FCS(row, q * 32 + 4 * u + 0);
            pn[4 * u + 1] = pv.y + mk * FCS(row, q * 32 + 4 * u + 1);
            pn[4 * u + 2] = pv.z + mk * FCS(row, q * 32 + 4 * u + 2);
            pn[4 * u + 3] = pv.w + mk * FCS(row, q * 32 + 4 * u + 3);
        }
#pragma unroll
        for (int v = 0; v < 32; v++) { s += pn[v]; sq = fmaf(pn[v], pn[v], sq); }
        s  += __shfl_down_sync(0xffffffffu, s,  2, 4);
        s  += __shfl_down_sync(0xffffffffu, s,  1, 4);
        sq += __shfl_down_sync(0xffffffffu, sq, 2, 4);
        sq += __shfl_down_sync(0xffffffffu, sq, 1, 4);
        s  = __shfl_sync(0xffffffffu, s,  0, 4);
        sq = __shfl_sync(0xffffffffu, sq, 0, 4);

        const float mu  = s * (1.f / 128.f);
        const float var = sq * (1.f / 128.f) - mu * mu;
        const float inv = rsqrtf(var + 1e-5f);

#pragma unroll
        for (int u = 0; u < 8; u++) {
            int d = q * 32 + 4 * u;
            float4 gv = *(const float4*)&gamma[d];
            float4 bv = *(const float4*)&beta[d];
            float4 o;
            o.x = (pn[4 * u + 0] - mu) * inv * gv.x + bv.x;
            o.y = (pn[4 * u + 1] - mu) * inv * gv.y + bv.y;
            o.z = (pn[4 * u + 2] - mu) * inv * gv.z + bv.z;
            o.w = (pn[4 * u + 3] - mu) * inv * gv.w + bv.w;
            *(float4*)&out[(size_t)pair * D + d] = o;
        }
    }
#undef F_LOAD
}
#undef FCS

// ---------------------------------------------------------------------------
extern "C" void kernel_launch(void* const* d_in, const int* in_sizes, int n_in,
                              void* d_out, int out_size) {
    const float* P     = (const float*)d_in[0];
    const float* mask  = (const float*)d_in[1];
    const float* Wl    = (const float*)d_in[2];
    const float* Wr    = (const float*)d_in[3];
    const float* Wo    = (const float*)d_in[4];
    const float* gamma = (const float*)d_in[5];
    const float* beta  = (const float*)d_in[6];
    float* out = (float*)d_out;

    cudaFuncSetAttribute(k_tri, cudaFuncAttributeMaxDynamicSharedMemorySize, T_SMEM);

    k_wt<<<64, 256>>>(Wo);
    k_proj<<<dim3(LL / 128, 2), 256>>>(P, mask, Wl, Wr);
    k_tri<<<dim3(L / 128, L / 128, H), 256, T_SMEM>>>();
    k_fin<<<LL / 64, 128>>>(P, mask, gamma, beta, out);
}

// round 14
// speedup vs baseline: 1.9095x; 1.0067x over previous
#include <cuda_runtime.h>
#include <cuda_fp16.h>
#include <cstdint>

#define L  384
#define D  128
#define H  128
#define LL (L * L)   // 147456

// Scratch — static device globals (no cudaMalloc allowed).
__device__ __half g_LhT[(size_t)H * LL];  // [h][i*L+k]  (fp16)
__device__ __half g_RhT[(size_t)H * LL];  // [h][j*L+k]  (fp16, j-major)
__device__ __half g_updT[(size_t)H * LL]; // [h][i*L+j]  (fp16)
__device__ __half g_Wo2h[D * H];          // [d][h] = fp16(W_out[d][h])

// ---------------------------------------------------------------------------
// helpers
// ---------------------------------------------------------------------------
__device__ __forceinline__ void mma16(float c[4], const unsigned a[4], const unsigned b[2]) {
    asm volatile(
        "mma.sync.aligned.m16n8k16.row.col.f32.f16.f16.f32 "
        "{%0,%1,%2,%3}, {%4,%5,%6,%7}, {%8,%9}, {%0,%1,%2,%3};"
        : "+f"(c[0]), "+f"(c[1]), "+f"(c[2]), "+f"(c[3])
        : "r"(a[0]), "r"(a[1]), "r"(a[2]), "r"(a[3]), "r"(b[0]), "r"(b[1]));
}

__device__ __forceinline__ void ldsm4h(unsigned r[4], const __half* p) {
    unsigned a = (unsigned)__cvta_generic_to_shared(p);
    asm volatile("ldmatrix.sync.aligned.m8n8.x4.shared.b16 {%0,%1,%2,%3}, [%4];"
                 : "=r"(r[0]), "=r"(r[1]), "=r"(r[2]), "=r"(r[3]) : "r"(a));
}
__device__ __forceinline__ void ldsm4t(unsigned r[4], const __half* p) {
    unsigned a = (unsigned)__cvta_generic_to_shared(p);
    asm volatile("ldmatrix.sync.aligned.m8n8.x4.trans.shared.b16 {%0,%1,%2,%3}, [%4];"
                 : "=r"(r[0]), "=r"(r[1]), "=r"(r[2]), "=r"(r[3]) : "r"(a));
}

__device__ __forceinline__ void cpa16(void* dst, const void* src) {
    unsigned sa = (unsigned)__cvta_generic_to_shared(dst);
    asm volatile("cp.async.cg.shared.global [%0], [%1], 16;" :: "r"(sa), "l"(src));
}
__device__ __forceinline__ void cpa_commit() { asm volatile("cp.async.commit_group;"); }
__device__ __forceinline__ void cpa_wait0()  { asm volatile("cp.async.wait_group 0;"); }
__device__ __forceinline__ void cpa_wait1()  { asm volatile("cp.async.wait_group 1;"); }

// ---------------------------------------------------------------------------
// Kernel 0: fp16-round W_out (native [d][h] order) -> g_Wo2h
// ---------------------------------------------------------------------------
__global__ __launch_bounds__(256) void k_wt(const float* __restrict__ Wo) {
    int idx = blockIdx.x * 256 + threadIdx.x;   // 16384
    g_Wo2h[idx] = __float2half_rn(Wo[idx]);
}

// ---------------------------------------------------------------------------
// Kernel 1: projection GEMM — fp16 mma + ldmatrix (round-12, committed).
// ---------------------------------------------------------------------------
#define PCS(n, m) smf[(n) * 132 + (m)]

__global__ __launch_bounds__(256) void k_proj(
    const float* __restrict__ P, const float* __restrict__ mask,
    const float* __restrict__ Wl, const float* __restrict__ Wr)
{
    __shared__ __align__(16) float smf[5120];   // 20,480 B (halves alias floats)
    __half* sm = (__half*)smf;
    float* mV = smf + 32 * 132 + 16;            // 128 mask vals (epilogue reuse)

    const int tid = threadIdx.x;
    const int wid = tid >> 5, lane = tid & 31;
    const int wm = wid & 3, wn = wid >> 2;
    const int group = lane >> 2, tid4 = lane & 3;
    const int bid = blockIdx.x;
    const bool isL = (blockIdx.y == 0);
    const float* __restrict__ W = isL ? Wl : Wr;

    int srcBase, srcStride, dmBase;
    if (isL) {
        srcBase = bid * 128;  srcStride = 1;  dmBase = bid * 128;
    } else {
        int j = bid / 3, k0p = (bid % 3) * 128;
        srcBase = k0p * L + j;  srcStride = L;  dmBase = j * L + k0p;
    }

    int aOff[2], bOff[4];
#pragma unroll
    for (int mt = 0; mt < 2; mt++)
        aOff[mt] = (wm * 32 + mt * 16 + (lane & 7) + 8 * ((lane >> 3) & 1)) * 40
                 + 8 * (lane >> 4);
#pragma unroll
    for (int p = 0; p < 4; p++)
        bOff[p] = 5120 + (wn * 64 + p * 16 + (lane & 7) + 8 * (lane >> 4)) * 40
                + 8 * ((lane >> 3) & 1);

    float acc[2][8][4];
#pragma unroll
    for (int mt = 0; mt < 2; mt++)
#pragma unroll
        for (int nt = 0; nt < 8; nt++)
#pragma unroll
            for (int v = 0; v < 4; v++) acc[mt][nt][v] = 0.f;

    const int mld = tid >> 3;          // 0..31 (+32p)
    const int kld = (tid & 7) * 4;     // 0..28

    float4 va[4], vb[4];
#define P_FETCH(k0)                                                                 \
    {                                                                               \
        _Pragma("unroll")                                                           \
        for (int p = 0; p < 4; p++) {                                               \
            int m = mld + p * 32;                                                   \
            va[p] = *(const float4*)&P[(size_t)(srcBase + (size_t)m * srcStride) * D + (k0) + kld]; \
            vb[p] = *(const float4*)&W[m * D + (k0) + kld];                         \
        }                                                                           \
    }
#define P_STORE()                                                                   \
    {                                                                               \
        _Pragma("unroll")                                                           \
        for (int p = 0; p < 4; p++) {                                               \
            int m = mld + p * 32;                                                   \
            __half2 a0 = __floats2half2_rn(va[p].x, va[p].y);                       \
            __half2 a1 = __floats2half2_rn(va[p].z, va[p].w);                       \
            __half2 b0 = __floats2half2_rn(vb[p].x, vb[p].y);                       \
            __half2 b1 = __floats2half2_rn(vb[p].z, vb[p].w);                       \
            *(unsigned*)&sm[m * 40 + kld]            = *(unsigned*)&a0;             \
            *(unsigned*)&sm[m * 40 + kld + 2]        = *(unsigned*)&a1;             \
            *(unsigned*)&sm[5120 + m * 40 + kld]     = *(unsigned*)&b0;             \
            *(unsigned*)&sm[5120 + m * 40 + kld + 2] = *(unsigned*)&b1;             \
        }                                                                           \
    }

    P_FETCH(0);

#pragma unroll 1
    for (int it = 0; it < 4; it++) {
        __syncthreads();
        P_STORE();
        __syncthreads();
        if (it < 3) P_FETCH((it + 1) * 32);
#pragma unroll
        for (int ks = 0; ks < 2; ks++) {
            const int k = ks * 16;
            unsigned a[2][4], b[4][4];
#pragma unroll
            for (int mt = 0; mt < 2; mt++)
                ldsm4h(a[mt], &sm[aOff[mt] + k]);
#pragma unroll
            for (int p = 0; p < 4; p++)
                ldsm4h(b[p], &sm[bOff[p] + k]);
#pragma unroll
            for (int mt = 0; mt < 2; mt++)
#pragma unroll
                for (int p = 0; p < 4; p++) {
                    mma16(acc[mt][2 * p],     a[mt], &b[p][0]);
                    mma16(acc[mt][2 * p + 1], a[mt], &b[p][2]);
                }
        }
    }
#undef P_FETCH
#undef P_STORE

    __syncthreads();
    if (tid < 128) mV[tid] = mask[dmBase + tid];
    __half* __restrict__ dst = isL ? g_LhT : g_RhT;

#pragma unroll 1
    for (int nc = 0; nc < 4; nc++) {
        __syncthreads();
        if (wn == (nc >> 1)) {
#pragma unroll
            for (int nt2 = 0; nt2 < 4; nt2++) {
                int nt = (nc & 1) * 4 + nt2;
                int cc = nt2 * 8 + 2 * tid4;
#pragma unroll
                for (int mt = 0; mt < 2; mt++) {
                    int r = wm * 32 + mt * 16 + group;
                    PCS(cc,     r)     = acc[mt][nt][0];
                    PCS(cc + 1, r)     = acc[mt][nt][1];
                    PCS(cc,     r + 8) = acc[mt][nt][2];
                    PCS(cc + 1, r + 8) = acc[mt][nt][3];
                }
            }
        }
        __syncthreads();
#pragma unroll
        for (int p = 0; p < 4; p++) {
            int nr = (tid >> 5) + p * 8;
            int m  = (tid & 31) * 4;
            __half2 h0 = __floats2half2_rn(PCS(nr, m + 0) * mV[m + 0],
                                           PCS(nr, m + 1) * mV[m + 1]);
            __half2 h1 = __floats2half2_rn(PCS(nr, m + 2) * mV[m + 2],
                                           PCS(nr, m + 3) * mV[m + 3]);
            uint2 u = make_uint2(*(unsigned*)&h0, *(unsigned*)&h1);
            *(uint2*)&dst[(size_t)(nc * 32 + nr) * LL + dmBase + m] = u;
        }
    }
#undef PCS
}

// ---------------------------------------------------------------------------
// Kernel 2: triangle einsum — fp16 mma + ldmatrix.
// BK=64, 2-stage cp.async, ONE syncthreads per iteration (canonical multistage:
// the post-sync load writes stage (it+1)%2, never the stage being computed).
// Tiles [row][64] halves, pitch 72 (verified conflict-free since R11 k_fin).
// Dynamic smem: 2 x 36,864 B = 73,728 B.
// ---------------------------------------------------------------------------
#define T_STG 18432                   // halves per stage: A 128*72 + B 128*72
#define T_SMEM (2 * T_STG * 2)        // 73,728 B
#define TCS(m, j)    smf[(m) * 132 + (j)]

__global__ __launch_bounds__(256, 2) void k_tri() {
    extern __shared__ __align__(16) float smf[];
    __half* sm = (__half*)smf;

    const int tid = threadIdx.x;
    const int wid = tid >> 5, lane = tid & 31;
    const int wm = wid & 3, wn = wid >> 2;
    const int group = lane >> 2, tid4 = lane & 3;
    const size_t hoff = (size_t)blockIdx.z * LL;
    const int i0 = blockIdx.y * 128;
    const int j0 = blockIdx.x * 128;

    const __half* __restrict__ A = g_LhT + hoff;
    const __half* __restrict__ B = g_RhT + hoff;

    int aOff[2], bOff[4];
#pragma unroll
    for (int mt = 0; mt < 2; mt++)
        aOff[mt] = (wm * 32 + mt * 16 + (lane & 7) + 8 * ((lane >> 3) & 1)) * 72
                 + 8 * (lane >> 4);
#pragma unroll
    for (int p = 0; p < 4; p++)
        bOff[p] = 9216 + (wn * 64 + p * 16 + (lane & 7) + 8 * (lane >> 4)) * 72
                + 8 * ((lane >> 3) & 1);

    float acc[2][8][4];
#pragma unroll
    for (int mt = 0; mt < 2; mt++)
#pragma unroll
        for (int nt = 0; nt < 8; nt++)
#pragma unroll
            for (int v = 0; v < 4; v++) acc[mt][nt][v] = 0.f;

    // stage loader: 1024 cpa16 A + 1024 cpa16 B (8 per thread), k0 in halves.
#define T_LOAD(s, k0)                                                              \
    {                                                                              \
        _Pragma("unroll")                                                          \
        for (int p = 0; p < 4; p++) {                                              \
            int task = tid + p * 256;                                              \
            int r = task >> 3, q = task & 7;                                       \
            cpa16(&sm[(s) * T_STG + r * 72 + q * 8],                               \
                  &A[(size_t)(i0 + r) * L + (k0) + q * 8]);                        \
            cpa16(&sm[(s) * T_STG + 9216 + r * 72 + q * 8],                        \
                  &B[(size_t)(j0 + r) * L + (k0) + q * 8]);                        \
        }                                                                          \
    }

    T_LOAD(0, 0);  cpa_commit();

#pragma unroll 1
    for (int it = 0; it < 6; it++) {
        const int s = it & 1;
        cpa_wait0();
        __syncthreads();
        if (it < 5) T_LOAD(s ^ 1, (it + 1) * 64);
        cpa_commit();
#pragma unroll
        for (int ks = 0; ks < 4; ks++) {
            const int k = ks * 16;
            unsigned a[2][4], b[4][4];
#pragma unroll
            for (int mt = 0; mt < 2; mt++)
                ldsm4h(a[mt], &sm[s * T_STG + aOff[mt] + k]);
#pragma unroll
            for (int p = 0; p < 4; p++)
                ldsm4h(b[p], &sm[s * T_STG + bOff[p] + k]);
#pragma unroll
            for (int mt = 0; mt < 2; mt++)
#pragma unroll
                for (int p = 0; p < 4; p++) {
                    mma16(acc[mt][2 * p],     a[mt], &b[p][0]);
                    mma16(acc[mt][2 * p + 1], a[mt], &b[p][2]);
                }
        }
    }
#undef T_LOAD

    // Epilogue: two 64-row chunks staged through smem, coalesced fp16 store.
#pragma unroll 1
    for (int mc = 0; mc < 2; mc++) {
        __syncthreads();
        if ((wm >> 1) == mc) {
#pragma unroll
            for (int nt = 0; nt < 8; nt++) {
                int cc = wn * 64 + nt * 8 + 2 * tid4;
#pragma unroll
                for (int mt = 0; mt < 2; mt++) {
                    int r = (wm & 1) * 32 + mt * 16 + group;
                    TCS(r,     cc)     = acc[mt][nt][0];
                    TCS(r,     cc + 1) = acc[mt][nt][1];
                    TCS(r + 8, cc)     = acc[mt][nt][2];
                    TCS(r + 8, cc + 1) = acc[mt][nt][3];
                }
            }
        }
        __syncthreads();
#pragma unroll
        for (int p = 0; p < 8; p++) {
            int row = (tid >> 5) + p * 8;
            int j   = (tid & 31) * 4;
            __half2 h0 = __floats2half2_rn(TCS(row, j + 0), TCS(row, j + 1));
            __half2 h1 = __floats2half2_rn(TCS(row, j + 2), TCS(row, j + 3));
            uint2 u = make_uint2(*(unsigned*)&h0, *(unsigned*)&h1);
            *(uint2*)&g_updT[hoff + (size_t)(i0 + mc * 64 + row) * L + j0 + j] = u;
        }
    }
#undef TCS
}

// ---------------------------------------------------------------------------
// Kernel 3: output projection (fp16 mma) + residual + mask + LN.
// 3-stage cp.async, ONE syncthreads per iteration.
// ---------------------------------------------------------------------------
#define F_STG 4224                    // halves per stage: A 16*72 + B 128*24
#define FCS(m, d)    sm[(m) * 132 + (d)]

__global__ __launch_bounds__(128, 4) void k_fin(
    const float* __restrict__ P, const float* __restrict__ mask,
    const float* __restrict__ gamma, const float* __restrict__ beta,
    float* __restrict__ out)
{
    __shared__ __align__(16) float sm[8448];   // 33,792 B
    __half* smh = (__half*)sm;

    const int tid = threadIdx.x;
    const int wid = tid >> 5, lane = tid & 31;
    const int wm = wid & 1, wn = wid >> 1;
    const int group = lane >> 2, tid4 = lane & 3;
    const int pairBase = blockIdx.x * 64;

    int aOff[2], bOff[4];
#pragma unroll
    for (int mt = 0; mt < 2; mt++)
        aOff[mt] = ((lane & 7) + 8 * (lane >> 4)) * 72
                 + wm * 32 + mt * 16 + 8 * ((lane >> 3) & 1);
#pragma unroll
    for (int p = 0; p < 4; p++)
        bOff[p] = 1152 + (wn * 64 + p * 16 + (lane & 7) + 8 * (lane >> 4)) * 24
                + 8 * ((lane >> 3) & 1);

    float acc[2][8][4];
#pragma unroll
    for (int mt = 0; mt < 2; mt++)
#pragma unroll
        for (int nt = 0; nt < 8; nt++)
#pragma unroll
            for (int v = 0; v < 4; v++) acc[mt][nt][v] = 0.f;

#define F_LOAD(s, k0)                                                                \
    {                                                                                \
        {                                                                            \
            int k = tid >> 3, m8 = (tid & 7) * 8;                                    \
            cpa16(&smh[(s) * F_STG + k * 72 + m8],                                   \
                  &g_updT[(size_t)((k0) + k) * LL + pairBase + m8]);                 \
        }                                                                            \
        _Pragma("unroll")                                                            \
        for (int p = 0; p < 2; p++) {                                                \
            int task = tid + p * 128;                                                \
            int n = task >> 1, q = (task & 1) * 8;                                   \
            cpa16(&smh[(s) * F_STG + 1152 + n * 24 + q],                             \
                  &g_Wo2h[n * H + (k0) + q]);                                        \
        }                                                                            \
    }

    F_LOAD(0, 0);  cpa_commit();
    F_LOAD(1, 16); cpa_commit();

#pragma unroll 1
    for (int it = 0; it < 8; it++) {
        const int s = it % 3;
        cpa_wait1();
        __syncthreads();
        if (it + 2 < 8) F_LOAD((it + 2) % 3, (it + 2) * 16);
        cpa_commit();
        unsigned a[2][4], b[4][4];
#pragma unroll
        for (int mt = 0; mt < 2; mt++)
            ldsm4t(a[mt], &smh[s * F_STG + aOff[mt]]);
#pragma unroll
        for (int p = 0; p < 4; p++)
            ldsm4h(b[p], &smh[s * F_STG + bOff[p]]);
#pragma unroll
        for (int mt = 0; mt < 2; mt++)
#pragma unroll
            for (int p = 0; p < 4; p++) {
                mma16(acc[mt][2 * p],     a[mt], &b[p][0]);
                mma16(acc[mt][2 * p + 1], a[mt], &b[p][2]);
            }
    }

    // Epilogue: stage whole 64x128 acc tile -> smem, then LayerNorm.
    __syncthreads();
#pragma unroll
    for (int nt = 0; nt < 8; nt++) {
        int cc = wn * 64 + nt * 8 + 2 * tid4;
#pragma unroll
        for (int mt = 0; mt < 2; mt++) {
            int r = wm * 32 + mt * 16 + group;
            FCS(r,     cc)     = acc[mt][nt][0];
            FCS(r,     cc + 1) = acc[mt][nt][1];
            FCS(r + 8, cc)     = acc[mt][nt][2];
            FCS(r + 8, cc + 1) = acc[mt][nt][3];
        }
    }
    __syncthreads();

#pragma unroll 1
    for (int h2 = 0; h2 < 2; h2++) {
        const int row = (tid >> 2) + h2 * 32;
        const int q   = tid & 3;
        const int pair = pairBase + row;
        const float mk = mask[pair];

        float pn[32];
        float s = 0.f, sq = 0.f;
#pragma unroll
        for (int u = 0; u < 8; u++) {
            float4 pv = *(const float4*)&P[(size_t)pair * D + q * 32 + 4 * u];
            pn[4 * u + 0] = pv.x + mk * FCS(row, q * 32 + 4 * u + 0);
            pn[4 * u + 1] = pv.y + mk * FCS(row, q * 32 + 4 * u + 1);
            pn[4 * u + 2] = pv.z + mk * FCS(row, q * 32 + 4 * u + 2);
            pn[4 * u + 3] = pv.w + mk * FCS(row, q * 32 + 4 * u + 3);
        }
#pragma unroll
        for (int v = 0; v < 32; v++) { s += pn[v]; sq = fmaf(pn[v], pn[v], sq); }
        s  += __shfl_down_sync(0xffffffffu, s,  2, 4);
        s  += __shfl_down_sync(0xffffffffu, s,  1, 4);
        sq += __shfl_down_sync(0xffffffffu, sq, 2, 4);
        sq += __shfl_down_sync(0xffffffffu, sq, 1, 4);
        s  = __shfl_sync(0xffffffffu, s,  0, 4);
        sq = __shfl_sync(0xffffffffu, sq, 0, 4);

        const float mu  = s * (1.f / 128.f);
        const float var = sq * (1.f / 128.f) - mu * mu;
        const float inv = rsqrtf(var + 1e-5f);

#pragma unroll
        for (int u = 0; u < 8; u++) {
            int d = q * 32 + 4 * u;
            float4 gv = *(const float4*)&gamma[d];
            float4 bv = *(const float4*)&beta[d];
            float4 o;
            o.x = (pn[4 * u + 0] - mu) * inv * gv.x + bv.x;
            o.y = (pn[4 * u + 1] - mu) * inv * gv.y + bv.y;
            o.z = (pn[4 * u + 2] - mu) * inv * gv.z + bv.z;
            o.w = (pn[4 * u + 3] - mu) * inv * gv.w + bv.w;
            *(float4*)&out[(size_t)pair * D + d] = o;
        }
    }
#undef F_LOAD
}
#undef FCS

// ---------------------------------------------------------------------------
extern "C" void kernel_launch(void* const* d_in, const int* in_sizes, int n_in,
                              void* d_out, int out_size) {
    const float* P     = (const float*)d_in[0];
    const float* mask  = (const float*)d_in[1];
    const float* Wl    = (const float*)d_in[2];
    const float* Wr    = (const float*)d_in[3];
    const float* Wo    = (const float*)d_in[4];
    const float* gamma = (const float*)d_in[5];
    const float* beta  = (const float*)d_in[6];
    float* out = (float*)d_out;

    cudaFuncSetAttribute(k_tri, cudaFuncAttributeMaxDynamicSharedMemorySize, T_SMEM);

    k_wt<<<64, 256>>>(Wo);
    k_proj<<<dim3(LL / 128, 2), 256>>>(P, mask, Wl, Wr);
    k_tri<<<dim3(L / 128, L / 128, H), 256, T_SMEM>>>();
    k_fin<<<LL / 64, 128>>>(P, mask, gamma, beta, out);
}